// round 1
// baseline (speedup 1.0000x reference)
#include <cuda_runtime.h>
#include <cstdint>

// Problem constants (Attention_26147760898609): B=8, T=2048, S=2048, D=512
#define BB 8
#define TT 2048
#define SN 2048
#define DD 512

// Scratch for projected keys (32 MB) — __device__ global per allocation rules.
__device__ float g_keys[(size_t)BB * SN * DD];

// ---------------- f32x2 packed helpers (sm_103a) ----------------
__device__ __forceinline__ void fma2(unsigned long long& d, unsigned long long a, unsigned long long b) {
    asm("fma.rn.f32x2 %0, %1, %2, %3;" : "=l"(d) : "l"(a), "l"(b), "l"(d));
}
__device__ __forceinline__ void mul2(unsigned long long& d, unsigned long long a, unsigned long long b) {
    asm("mul.rn.f32x2 %0, %1, %2;" : "=l"(d) : "l"(a), "l"(b));
}
__device__ __forceinline__ unsigned long long pack2(float lo, float hi) {
    unsigned long long r;
    asm("mov.b64 %0, {%1, %2};" : "=l"(r) : "f"(lo), "f"(hi));
    return r;
}
__device__ __forceinline__ float sum2(unsigned long long v) {
    float lo, hi;
    asm("mov.b64 {%0, %1}, %2;" : "=f"(lo), "=f"(hi) : "l"(v));
    return lo + hi;
}

// =====================================================================
// Kernel A: keys[n][e] = sum_d attn[n][d] * W[e][d] + bias[e]
//   n in [0, B*S), 64x64 tile per CTA, K-chunks of 64, f32x2 packed.
// =====================================================================
__global__ __launch_bounds__(256) void keys_gemm_kernel(
    const float* __restrict__ A,      // [B*S, D]
    const float* __restrict__ W,      // [D, D] row e has W[e][:]
    const float* __restrict__ bias)   // [D]
{
    __shared__ unsigned long long sA[32][66];  // [d2][m] packed {A[m][2d2],A[m][2d2+1]}
    __shared__ unsigned long long sW[32][66];  // [d2][e]

    const int tid = threadIdx.x;
    const int tm = tid >> 4;        // 0..15
    const int ts = tid & 15;        // 0..15
    const int n0 = blockIdx.y * 64;
    const int e0 = blockIdx.x * 64;

    const float* Ab = A + (size_t)n0 * DD;
    const float* Wb = W + (size_t)e0 * DD;

    unsigned long long acc[16];
#pragma unroll
    for (int i = 0; i < 16; i++) acc[i] = 0ULL;

    const int lrow = tm;            // 0..15
    const int lcol = ts * 4;        // 0..60
    const int ld2  = ts * 2;

    float4 ra[4], rw[4];
#pragma unroll
    for (int i = 0; i < 4; i++) {
        ra[i] = *(const float4*)(Ab + (size_t)(i * 16 + lrow) * DD + lcol);
        rw[i] = *(const float4*)(Wb + (size_t)(i * 16 + lrow) * DD + lcol);
    }

    for (int kk = 0; kk < 8; kk++) {
#pragma unroll
        for (int i = 0; i < 4; i++) {
            int row = i * 16 + lrow;
            sA[ld2][row]     = pack2(ra[i].x, ra[i].y);
            sA[ld2 + 1][row] = pack2(ra[i].z, ra[i].w);
            sW[ld2][row]     = pack2(rw[i].x, rw[i].y);
            sW[ld2 + 1][row] = pack2(rw[i].z, rw[i].w);
        }
        __syncthreads();
        if (kk < 7) {
            int dg = (kk + 1) * 64 + lcol;
#pragma unroll
            for (int i = 0; i < 4; i++) {
                ra[i] = *(const float4*)(Ab + (size_t)(i * 16 + lrow) * DD + dg);
                rw[i] = *(const float4*)(Wb + (size_t)(i * 16 + lrow) * DD + dg);
            }
        }
#pragma unroll 8
        for (int d = 0; d < 32; d++) {
            ulonglong2 qa = *(const ulonglong2*)&sA[d][tm * 4];
            ulonglong2 qb = *(const ulonglong2*)&sA[d][tm * 4 + 2];
            ulonglong2 ka = *(const ulonglong2*)&sW[d][ts * 4];
            ulonglong2 kb = *(const ulonglong2*)&sW[d][ts * 4 + 2];
            unsigned long long qm[4] = {qa.x, qa.y, qb.x, qb.y};
            unsigned long long kn[4] = {ka.x, ka.y, kb.x, kb.y};
#pragma unroll
            for (int i = 0; i < 4; i++)
#pragma unroll
                for (int j = 0; j < 4; j++)
                    fma2(acc[i * 4 + j], qm[i], kn[j]);
        }
        __syncthreads();
    }

    float bv[4];
#pragma unroll
    for (int j = 0; j < 4; j++) bv[j] = bias[e0 + ts * 4 + j];

#pragma unroll
    for (int i = 0; i < 4; i++) {
        float4 o;
        o.x = sum2(acc[i * 4 + 0]) + bv[0];
        o.y = sum2(acc[i * 4 + 1]) + bv[1];
        o.z = sum2(acc[i * 4 + 2]) + bv[2];
        o.w = sum2(acc[i * 4 + 3]) + bv[3];
        *(float4*)(g_keys + (size_t)(n0 + tm * 4 + i) * DD + e0 + ts * 4) = o;
    }
}

// =====================================================================
// Kernel B: fused flash attention, fp32 + f32x2 packed FMAs.
//   Q = main_input [B,T,D], K = g_keys [B,S,D], V = attn_input [B,S,D]
//   CTA: 64 query rows, 256 threads, S-tiles of 64, D-chunks of 64.
// =====================================================================
struct SmemB {
    unsigned long long q2[256][66];  // [d2][m]  {Q[m][2d2],Q[m][2d2+1]}
    unsigned long long k2[32][66];   // [d2][s]
    unsigned long long v2[32][66];   // [s2][d]  {V[2s2][d],V[2s2+1][d]}
    unsigned long long p2[32][66];   // [s2][m]  {P[m][2s2],P[m][2s2+1]}
    float red[64][17];
    float mi[64];
    float li[64];
    float alpha[64];
};
#define SMEM_B_BYTES ((int)sizeof(SmemB))

extern __shared__ unsigned char smem_raw[];

__global__ __launch_bounds__(256, 1) void flash_kernel(
    const float* __restrict__ Q,     // main_input
    const float* __restrict__ V,     // attn_input (raw values)
    float* __restrict__ out)
{
    SmemB* sm = (SmemB*)smem_raw;
    const int tid = threadIdx.x;
    const int b = blockIdx.y;
    const int tblk = blockIdx.x;
    const int tm = tid >> 4;
    const int ts = tid & 15;
    const int lrow = tm;
    const int lcol = ts * 4;
    const int ld2  = ts * 2;

    const float* Qb = Q + ((size_t)b * TT + (size_t)tblk * 64) * DD;
    const float* Kb = g_keys + (size_t)b * SN * DD;
    const float* Vb = V + (size_t)b * SN * DD;

    // ---- Load Q tile [64][512] into q2 (packed, transposed) ----
#pragma unroll 4
    for (int i = 0; i < 32; i++) {
        int idx = tid + i * 256;     // over 64 rows x 128 float4 cols
        int row = idx >> 7;
        int c4 = idx & 127;
        float4 v = *(const float4*)(Qb + (size_t)row * DD + c4 * 4);
        int d2 = c4 * 2;
        sm->q2[d2][row]     = pack2(v.x, v.y);
        sm->q2[d2 + 1][row] = pack2(v.z, v.w);
    }
    if (tid < 64) {
        sm->mi[tid] = -3.4e38f;
        sm->li[tid] = 0.f;
    }

    unsigned long long o2[4][32];
#pragma unroll
    for (int i = 0; i < 4; i++)
#pragma unroll
        for (int j = 0; j < 32; j++) o2[i][j] = 0ULL;

    __syncthreads();

    for (int s0 = 0; s0 < SN; s0 += 64) {
        // =============== Phase 1: scores = Q * K^T ===============
        unsigned long long acc[16];
#pragma unroll
        for (int i = 0; i < 16; i++) acc[i] = 0ULL;

        const float* Kt = Kb + (size_t)s0 * DD;
        float4 rk[4];
#pragma unroll
        for (int i = 0; i < 4; i++)
            rk[i] = *(const float4*)(Kt + (size_t)(i * 16 + lrow) * DD + lcol);

        for (int c = 0; c < 8; c++) {
#pragma unroll
            for (int i = 0; i < 4; i++) {
                int row = i * 16 + lrow;
                sm->k2[ld2][row]     = pack2(rk[i].x, rk[i].y);
                sm->k2[ld2 + 1][row] = pack2(rk[i].z, rk[i].w);
            }
            __syncthreads();
            if (c < 7) {
                int dg = (c + 1) * 64 + lcol;
#pragma unroll
                for (int i = 0; i < 4; i++)
                    rk[i] = *(const float4*)(Kt + (size_t)(i * 16 + lrow) * DD + dg);
            }
            const int dbase = c * 32;
#pragma unroll 8
            for (int d = 0; d < 32; d++) {
                ulonglong2 qa = *(const ulonglong2*)&sm->q2[dbase + d][tm * 4];
                ulonglong2 qb = *(const ulonglong2*)&sm->q2[dbase + d][tm * 4 + 2];
                ulonglong2 ka = *(const ulonglong2*)&sm->k2[d][ts * 4];
                ulonglong2 kb = *(const ulonglong2*)&sm->k2[d][ts * 4 + 2];
                unsigned long long qm[4] = {qa.x, qa.y, qb.x, qb.y};
                unsigned long long kn[4] = {ka.x, ka.y, kb.x, kb.y};
#pragma unroll
                for (int i = 0; i < 4; i++)
#pragma unroll
                    for (int j = 0; j < 4; j++)
                        fma2(acc[i * 4 + j], qm[i], kn[j]);
            }
            __syncthreads();
        }

        float s[16];
#pragma unroll
        for (int i = 0; i < 16; i++) s[i] = sum2(acc[i]);

        // =============== Phase 2: online softmax ===============
#pragma unroll
        for (int mi_ = 0; mi_ < 4; mi_++) {
            float lmax = fmaxf(fmaxf(s[mi_ * 4], s[mi_ * 4 + 1]),
                               fmaxf(s[mi_ * 4 + 2], s[mi_ * 4 + 3]));
            sm->red[tm * 4 + mi_][ts] = lmax;
        }
        __syncthreads();
        if (tid < 64) {
            float tmax = sm->red[tid][0];
#pragma unroll
            for (int j = 1; j < 16; j++) tmax = fmaxf(tmax, sm->red[tid][j]);
            float mold = sm->mi[tid];
            float mnew = fmaxf(mold, tmax);
            float a = (mold > -1e37f) ? __expf(mold - mnew) : 0.0f;
            sm->mi[tid] = mnew;
            sm->alpha[tid] = a;
            sm->li[tid] *= a;
        }
        __syncthreads();
#pragma unroll
        for (int mi_ = 0; mi_ < 4; mi_++) {
            int m = tm * 4 + mi_;
            float mnew = sm->mi[m];
            float p0 = __expf(s[mi_ * 4 + 0] - mnew);
            float p1 = __expf(s[mi_ * 4 + 1] - mnew);
            float p2v = __expf(s[mi_ * 4 + 2] - mnew);
            float p3 = __expf(s[mi_ * 4 + 3] - mnew);
            sm->red[m][ts] = (p0 + p1) + (p2v + p3);
            sm->p2[ts * 2][m]     = pack2(p0, p1);
            sm->p2[ts * 2 + 1][m] = pack2(p2v, p3);
            float a = sm->alpha[m];
            if (a != 1.0f) {
                unsigned long long a2 = pack2(a, a);
#pragma unroll
                for (int j = 0; j < 32; j++) mul2(o2[mi_][j], a2, o2[mi_][j]);
            }
        }
        __syncthreads();
        if (tid < 64) {
            float tsum = 0.f;
#pragma unroll
            for (int j = 0; j < 16; j++) tsum += sm->red[tid][j];
            sm->li[tid] += tsum;
        }

        // =============== Phase 3: O += P * V ===============
        const float* Vt = Vb + (size_t)s0 * DD;
        float4 rv[4];
#pragma unroll
        for (int i = 0; i < 4; i++)
            rv[i] = *(const float4*)(Vt + (size_t)(i * 16 + lrow) * DD + lcol);

        for (int c = 0; c < 8; c++) {
#pragma unroll
            for (int i = 0; i < 4; i++) {
                int srow = i * 16 + lrow;
                int s2i = srow >> 1;
                int half = srow & 1;
                float* dst = ((float*)&sm->v2[s2i][lcol]) + half;
                dst[0] = rv[i].x;
                dst[2] = rv[i].y;
                dst[4] = rv[i].z;
                dst[6] = rv[i].w;
            }
            __syncthreads();
            if (c < 7) {
                int dg = (c + 1) * 64 + lcol;
#pragma unroll
                for (int i = 0; i < 4; i++)
                    rv[i] = *(const float4*)(Vt + (size_t)(i * 16 + lrow) * DD + dg);
            }
#pragma unroll 8
            for (int s2i = 0; s2i < 32; s2i++) {
                ulonglong2 pa = *(const ulonglong2*)&sm->p2[s2i][tm * 4];
                ulonglong2 pb = *(const ulonglong2*)&sm->p2[s2i][tm * 4 + 2];
                ulonglong2 va = *(const ulonglong2*)&sm->v2[s2i][ts * 4];
                ulonglong2 vb = *(const ulonglong2*)&sm->v2[s2i][ts * 4 + 2];
                unsigned long long pm[4] = {pa.x, pa.y, pb.x, pb.y};
                unsigned long long vd[4] = {va.x, va.y, vb.x, vb.y};
#pragma unroll
                for (int i = 0; i < 4; i++)
#pragma unroll
                    for (int j = 0; j < 4; j++)
                        fma2(o2[i][c * 4 + j], pm[i], vd[j]);
            }
            __syncthreads();
        }
    }

    // ---- Epilogue: out = O / l ----
    float inv[4];
#pragma unroll
    for (int mi_ = 0; mi_ < 4; mi_++) inv[mi_] = 1.0f / sm->li[tm * 4 + mi_];

#pragma unroll
    for (int mi_ = 0; mi_ < 4; mi_++) {
        size_t rowoff = ((size_t)b * TT + (size_t)tblk * 64 + tm * 4 + mi_) * DD;
#pragma unroll
        for (int c = 0; c < 8; c++) {
            float4 r;
            r.x = sum2(o2[mi_][c * 4 + 0]) * inv[mi_];
            r.y = sum2(o2[mi_][c * 4 + 1]) * inv[mi_];
            r.z = sum2(o2[mi_][c * 4 + 2]) * inv[mi_];
            r.w = sum2(o2[mi_][c * 4 + 3]) * inv[mi_];
            *(float4*)(out + rowoff + c * 64 + ts * 4) = r;
        }
    }
}

// =====================================================================
// kernel_launch
//   d_in[0] = main_input  [B,T,D] f32
//   d_in[1] = attn_input  [B,S,D] f32
//   d_in[2] = W_f         [D,D]   f32
//   d_in[3] = b_f         [D]     f32
//   d_out   = out         [B,T,D] f32
// =====================================================================
extern "C" void kernel_launch(void* const* d_in, const int* in_sizes, int n_in,
                              void* d_out, int out_size) {
    const float* main_in = (const float*)d_in[0];
    const float* attn_in = (const float*)d_in[1];
    const float* W_f = (const float*)d_in[2];
    const float* b_f = (const float*)d_in[3];
    float* out = (float*)d_out;

    // Kernel A: keys projection GEMM  [B*S, D] x [D, D]^T
    {
        dim3 grid(DD / 64, (BB * SN) / 64);  // (8, 256)
        keys_gemm_kernel<<<grid, 256>>>(attn_in, W_f, b_f);
    }

    // Kernel B: fused flash attention
    {
        cudaFuncSetAttribute(flash_kernel,
                             cudaFuncAttributeMaxDynamicSharedMemorySize,
                             SMEM_B_BYTES);
        dim3 grid(TT / 64, BB);  // (32, 8)
        flash_kernel<<<grid, 256, SMEM_B_BYTES>>>(main_in, attn_in, out);
    }
}

// round 2
// speedup vs baseline: 1.7740x; 1.7740x over previous
#include <cuda_runtime.h>
#include <cstdint>

// Problem constants (Attention_26147760898609): B=8, T=2048, S=2048, D=512
#define BB 8
#define TT 2048
#define SN 2048
#define DD 512

typedef unsigned long long u64;

// Scratch (device globals per allocation rules)
__device__ float g_keys[(size_t)BB * SN * DD];     // 32 MB
__device__ float g_scores[(size_t)BB * TT * SN];   // 128 MB

// ---------------- f32x2 packed helpers (sm_103a) ----------------
__device__ __forceinline__ void fma2(u64& d, u64 a, u64 b) {
    asm("fma.rn.f32x2 %0, %1, %2, %3;" : "=l"(d) : "l"(a), "l"(b), "l"(d));
}
__device__ __forceinline__ u64 pack2(float lo, float hi) {
    u64 r;
    asm("mov.b64 %0, {%1, %2};" : "=l"(r) : "f"(lo), "f"(hi));
    return r;
}
__device__ __forceinline__ float sum2(u64 v) {
    float lo, hi;
    asm("mov.b64 {%0, %1}, %2;" : "=f"(lo), "=f"(hi) : "l"(v));
    return lo + hi;
}

// =====================================================================
// Generic f32x2 GEMM: C[m][n] (+= bias[n]) = sum_k A[m][k] * B(k, n)
//   TRANS_B=false: Bm is [N][ldb] row-major, B(k,n) = Bm[n][k]  (NT gemm)
//   TRANS_B=true : Bm is [K][ldb] row-major, B(k,n) = Bm[k][n]  (NN gemm)
// CTA tile 128x128, 256 threads, 8x8 per thread (2x2 slabs of 4x4),
// contraction chunk 32, register-prefetch single-buffer smem.
// blockIdx.z = batch (strides in elements).
// =====================================================================
template <bool TRANS_B, bool ADD_BIAS>
__global__ __launch_bounds__(256, 1) void gemm_f32x2(
    const float* __restrict__ A,
    const float* __restrict__ Bm,
    const float* __restrict__ bias,
    float* __restrict__ C,
    int K, int lda, int ldb, int ldc,
    long strideA, long strideB, long strideC)
{
    __shared__ u64 a2[16][132];   // [d2][m]  pair = {A[m][2d2], A[m][2d2+1]}
    __shared__ u64 b2[16][132];   // [d2][n]  pair along contraction

    const int tid = threadIdx.x;
    const int m0 = blockIdx.y * 128;
    const int n0 = blockIdx.x * 128;

    const float* Ab = A + (long)blockIdx.z * strideA + (size_t)m0 * lda;
    const float* Bb = Bm + (long)blockIdx.z * strideB;
    float* Cb = C + (long)blockIdx.z * strideC;

    const int arow = tid >> 3;    // 0..31
    const int acol4 = tid & 7;    // 0..7  -> 4 contraction elems
    const int vrow = tid >> 5;    // 0..7   (TRANS_B staging)
    const int vcol4 = tid & 31;   // 0..31  -> 4 n elems

    u64 acc[64];
#pragma unroll
    for (int i = 0; i < 64; i++) acc[i] = 0ULL;

    float4 ra[4], rb[4];
#pragma unroll
    for (int i = 0; i < 4; i++)
        ra[i] = *(const float4*)(Ab + (size_t)(arow + i * 32) * lda + acol4 * 4);
    if (!TRANS_B) {
#pragma unroll
        for (int i = 0; i < 4; i++)
            rb[i] = *(const float4*)(Bb + (size_t)(n0 + arow + i * 32) * ldb + acol4 * 4);
    } else {
#pragma unroll
        for (int i = 0; i < 4; i++)
            rb[i] = *(const float4*)(Bb + (size_t)(vrow + i * 8) * ldb + n0 + vcol4 * 4);
    }

    const int tm4 = (tid >> 4) * 4;   // m slab base (and m slab + 64)
    const int ts4 = (tid & 15) * 4;   // n slab base (and n slab + 64)

    const int nch = K / 32;
    for (int c = 0; c < nch; c++) {
        // ---- stage current chunk to smem ----
#pragma unroll
        for (int i = 0; i < 4; i++) {
            int m = arow + i * 32;
            a2[acol4 * 2][m]     = pack2(ra[i].x, ra[i].y);
            a2[acol4 * 2 + 1][m] = pack2(ra[i].z, ra[i].w);
        }
        if (!TRANS_B) {
#pragma unroll
            for (int i = 0; i < 4; i++) {
                int n = arow + i * 32;
                b2[acol4 * 2][n]     = pack2(rb[i].x, rb[i].y);
                b2[acol4 * 2 + 1][n] = pack2(rb[i].z, rb[i].w);
            }
        } else {
#pragma unroll
            for (int i = 0; i < 4; i++) {
                int s = vrow + i * 8;
                float* dst = ((float*)&b2[s >> 1][vcol4 * 4]) + (s & 1);
                dst[0] = rb[i].x;
                dst[2] = rb[i].y;
                dst[4] = rb[i].z;
                dst[6] = rb[i].w;
            }
        }
        __syncthreads();

        // ---- prefetch next chunk into registers ----
        if (c + 1 < nch) {
            int kc = (c + 1) * 32;
#pragma unroll
            for (int i = 0; i < 4; i++)
                ra[i] = *(const float4*)(Ab + (size_t)(arow + i * 32) * lda + kc + acol4 * 4);
            if (!TRANS_B) {
#pragma unroll
                for (int i = 0; i < 4; i++)
                    rb[i] = *(const float4*)(Bb + (size_t)(n0 + arow + i * 32) * ldb + kc + acol4 * 4);
            } else {
#pragma unroll
                for (int i = 0; i < 4; i++)
                    rb[i] = *(const float4*)(Bb + (size_t)(kc + vrow + i * 8) * ldb + n0 + vcol4 * 4);
            }
        }

        // ---- inner product: 16 packed contraction steps ----
#pragma unroll
        for (int d2 = 0; d2 < 16; d2++) {
            u64 am[8], bn[8];
            *(ulonglong2*)&am[0] = *(const ulonglong2*)&a2[d2][tm4];
            *(ulonglong2*)&am[2] = *(const ulonglong2*)&a2[d2][tm4 + 2];
            *(ulonglong2*)&am[4] = *(const ulonglong2*)&a2[d2][64 + tm4];
            *(ulonglong2*)&am[6] = *(const ulonglong2*)&a2[d2][64 + tm4 + 2];
            *(ulonglong2*)&bn[0] = *(const ulonglong2*)&b2[d2][ts4];
            *(ulonglong2*)&bn[2] = *(const ulonglong2*)&b2[d2][ts4 + 2];
            *(ulonglong2*)&bn[4] = *(const ulonglong2*)&b2[d2][64 + ts4];
            *(ulonglong2*)&bn[6] = *(const ulonglong2*)&b2[d2][64 + ts4 + 2];
#pragma unroll
            for (int i = 0; i < 8; i++)
#pragma unroll
                for (int j = 0; j < 8; j++)
                    fma2(acc[i * 8 + j], am[i], bn[j]);
        }
        __syncthreads();
    }

    // ---- epilogue ----
    float bv[8];
    if (ADD_BIAS) {
        *(float4*)&bv[0] = *(const float4*)(bias + n0 + ts4);
        *(float4*)&bv[4] = *(const float4*)(bias + n0 + 64 + ts4);
    }
#pragma unroll
    for (int i = 0; i < 8; i++) {
        int m = m0 + ((i < 4) ? (tm4 + i) : (64 + tm4 + i - 4));
#pragma unroll
        for (int js = 0; js < 2; js++) {
            float4 o;
            o.x = sum2(acc[i * 8 + js * 4 + 0]);
            o.y = sum2(acc[i * 8 + js * 4 + 1]);
            o.z = sum2(acc[i * 8 + js * 4 + 2]);
            o.w = sum2(acc[i * 8 + js * 4 + 3]);
            if (ADD_BIAS) {
                o.x += bv[js * 4 + 0];
                o.y += bv[js * 4 + 1];
                o.z += bv[js * 4 + 2];
                o.w += bv[js * 4 + 3];
            }
            *(float4*)(Cb + (size_t)m * ldc + n0 + js * 64 + ts4) = o;
        }
    }
}

// =====================================================================
// Row softmax over S=2048, in place. One CTA (256 threads) per row.
// =====================================================================
__global__ __launch_bounds__(256) void softmax_kernel(float* __restrict__ P)
{
    __shared__ float red[8];
    const int tid = threadIdx.x;
    const int lane = tid & 31;
    const int warp = tid >> 5;
    float* row = P + (size_t)blockIdx.x * SN;

    float4 v0 = ((const float4*)row)[tid];
    float4 v1 = ((const float4*)row)[tid + 256];

    float m = fmaxf(fmaxf(fmaxf(v0.x, v0.y), fmaxf(v0.z, v0.w)),
                    fmaxf(fmaxf(v1.x, v1.y), fmaxf(v1.z, v1.w)));
#pragma unroll
    for (int o = 16; o > 0; o >>= 1)
        m = fmaxf(m, __shfl_xor_sync(0xffffffffu, m, o));
    if (lane == 0) red[warp] = m;
    __syncthreads();
    float mall = red[0];
#pragma unroll
    for (int k = 1; k < 8; k++) mall = fmaxf(mall, red[k]);
    __syncthreads();

    v0.x = __expf(v0.x - mall); v0.y = __expf(v0.y - mall);
    v0.z = __expf(v0.z - mall); v0.w = __expf(v0.w - mall);
    v1.x = __expf(v1.x - mall); v1.y = __expf(v1.y - mall);
    v1.z = __expf(v1.z - mall); v1.w = __expf(v1.w - mall);

    float s = (v0.x + v0.y) + (v0.z + v0.w) + (v1.x + v1.y) + (v1.z + v1.w);
#pragma unroll
    for (int o = 16; o > 0; o >>= 1)
        s += __shfl_xor_sync(0xffffffffu, s, o);
    if (lane == 0) red[warp] = s;
    __syncthreads();
    float sall = red[0];
#pragma unroll
    for (int k = 1; k < 8; k++) sall += red[k];
    float inv = 1.0f / sall;

    v0.x *= inv; v0.y *= inv; v0.z *= inv; v0.w *= inv;
    v1.x *= inv; v1.y *= inv; v1.z *= inv; v1.w *= inv;
    ((float4*)row)[tid] = v0;
    ((float4*)row)[tid + 256] = v1;
}

// =====================================================================
// kernel_launch
//   d_in[0] = main_input [B,T,D] f32   (queries)
//   d_in[1] = attn_input [B,S,D] f32   (projected to keys; raw values)
//   d_in[2] = W_f [D,D] f32
//   d_in[3] = b_f [D]   f32
//   d_out   = out [B,T,D] f32
// =====================================================================
extern "C" void kernel_launch(void* const* d_in, const int* in_sizes, int n_in,
                              void* d_out, int out_size) {
    const float* main_in = (const float*)d_in[0];
    const float* attn_in = (const float*)d_in[1];
    const float* W_f = (const float*)d_in[2];
    const float* b_f = (const float*)d_in[3];
    float* out = (float*)d_out;

    float* keys_p = nullptr;
    float* scores_p = nullptr;
    cudaGetSymbolAddress((void**)&keys_p, g_keys);
    cudaGetSymbolAddress((void**)&scores_p, g_scores);

    // 1) keys = attn_in @ W_f^T + b_f   : M=B*S=16384, N=512, K=512 (NT)
    {
        dim3 grid(DD / 128, (BB * SN) / 128, 1);  // (4, 128, 1)
        gemm_f32x2<false, true><<<grid, 256>>>(
            attn_in, W_f, b_f, keys_p,
            DD, DD, DD, DD, 0, 0, 0);
    }

    // 2) scores[b] = Q[b] @ keys[b]^T  : M=T=2048, N=S=2048, K=512 (NT), per batch
    {
        dim3 grid(SN / 128, TT / 128, BB);        // (16, 16, 8)
        gemm_f32x2<false, false><<<grid, 256>>>(
            main_in, keys_p, nullptr, scores_p,
            DD, DD, DD, SN,
            (long)TT * DD, (long)SN * DD, (long)TT * SN);
    }

    // 3) softmax rows (in place)
    softmax_kernel<<<BB * TT, 256>>>(scores_p);

    // 4) out[b] = P[b] @ V[b]          : M=T=2048, N=D=512, K=S=2048 (NN)
    {
        dim3 grid(DD / 128, TT / 128, BB);        // (4, 16, 8)
        gemm_f32x2<true, false><<<grid, 256>>>(
            scores_p, attn_in, nullptr, out,
            SN, SN, DD, DD,
            (long)TT * SN, (long)SN * DD, (long)TT * DD);
    }
}

// round 4
// speedup vs baseline: 4.4611x; 2.5148x over previous
#include <cuda_runtime.h>
#include <cuda_bf16.h>
#include <cstdint>

// Problem constants: B=8, T=2048, S=2048, D=512
#define BB 8
#define TT 2048
#define SN 2048
#define DD 512

typedef uint32_t u32;
typedef uint64_t u64;

// ----------------- device scratch (allocation-free rules) -----------------
__device__ __nv_bfloat16 g_Qh[(size_t)BB * TT * DD];
__device__ __nv_bfloat16 g_Ql[(size_t)BB * TT * DD];
__device__ __nv_bfloat16 g_Ah[(size_t)BB * SN * DD];   // attn_input split (K-major)
__device__ __nv_bfloat16 g_Al[(size_t)BB * SN * DD];
__device__ __nv_bfloat16 g_Vth[(size_t)BB * DD * SN];  // attn_input transposed [B][D][S]
__device__ __nv_bfloat16 g_Vtl[(size_t)BB * DD * SN];
__device__ __nv_bfloat16 g_Wh[(size_t)DD * DD];
__device__ __nv_bfloat16 g_Wl[(size_t)DD * DD];
__device__ __nv_bfloat16 g_Kh[(size_t)BB * SN * DD];
__device__ __nv_bfloat16 g_Kl[(size_t)BB * SN * DD];
__device__ float g_P[(size_t)BB * TT * SN];            // 128 MB
__device__ __nv_bfloat16 g_Ph[(size_t)BB * TT * SN];   // 64 MB
__device__ __nv_bfloat16 g_Pl[(size_t)BB * TT * SN];   // 64 MB

// ----------------- helpers -----------------
__device__ __forceinline__ u32 smem_u32(const void* p) {
    u32 a;
    asm("{ .reg .u64 t; cvta.to.shared.u64 t, %1; cvt.u32.u64 %0, t; }" : "=r"(a) : "l"(p));
    return a;
}
// pack two fp32 -> bf16x2 word; lo half = second arg
__device__ __forceinline__ u32 packbf(float hi_elem, float lo_elem) {
    u32 r;
    asm("cvt.rn.bf16x2.f32 %0, %1, %2;" : "=r"(r) : "f"(hi_elem), "f"(lo_elem));
    return r;
}
__device__ __forceinline__ float lo_as_f32(u32 p) { return __uint_as_float(p << 16); }
__device__ __forceinline__ float hi_as_f32(u32 p) { return __uint_as_float(p & 0xFFFF0000u); }

__device__ __forceinline__ void cp16(u32 dst, const void* src) {
    asm volatile("cp.async.cg.shared.global [%0], [%1], 16;" :: "r"(dst), "l"(src));
}
__device__ __forceinline__ void cp_commit() {
    asm volatile("cp.async.commit_group;" ::: "memory");
}
template <int N>
__device__ __forceinline__ void cp_wait() {
    asm volatile("cp.async.wait_group %0;" :: "n"(N) : "memory");
}

__device__ __forceinline__ void ldm_x4(u32* r, u32 addr) {
    asm volatile("ldmatrix.sync.aligned.m8n8.x4.shared.b16 {%0,%1,%2,%3}, [%4];"
                 : "=r"(r[0]), "=r"(r[1]), "=r"(r[2]), "=r"(r[3]) : "r"(addr));
}
__device__ __forceinline__ void mma16816(float* d, const u32* a, const u32* b) {
    asm volatile(
        "mma.sync.aligned.m16n8k16.row.col.f32.bf16.bf16.f32 "
        "{%0,%1,%2,%3}, {%4,%5,%6,%7}, {%8,%9}, {%0,%1,%2,%3};"
        : "+f"(d[0]), "+f"(d[1]), "+f"(d[2]), "+f"(d[3])
        : "r"(a[0]), "r"(a[1]), "r"(a[2]), "r"(a[3]), "r"(b[0]), "r"(b[1]));
}

// ----------------- GEMM smem layout -----------------
// Tiles: 128 rows x 32 bf16 (64B data), row pitch 80B (conflict-free ldmatrix).
// Stage = {Ah, Al, Bh, Bl}, each 128*80 = 10240B -> 40960B; double buffered.
#define TPITCH 80
#define TILEB (128 * TPITCH)
#define STAGEB (4 * TILEB)
#define SMEM_TOTAL (2 * STAGEB)

// =====================================================================
// NT split-bf16 GEMM: C[m][n] = sum_k A[m][k]*B[n][k] (+bias[n])
//   A,B given as hi/lo bf16 row-major (K-major). 3 passes: hh+hl+lh.
//   CTA 128x128, 8 warps (64x32 warp tile), K-chunk 32, cp.async x2 buf.
// =====================================================================
template <bool WRITE_SPLIT, bool ADD_BIAS>
__global__ void __launch_bounds__(256, 1) gemm_mma(
    const __nv_bfloat16* __restrict__ Ah_, const __nv_bfloat16* __restrict__ Al_,
    const __nv_bfloat16* __restrict__ Bh_, const __nv_bfloat16* __restrict__ Bl_,
    const float* __restrict__ bias,
    float* __restrict__ Cf, __nv_bfloat16* __restrict__ Ch, __nv_bfloat16* __restrict__ Cl,
    int K, int lda, int ldb, int ldc,
    long sA, long sB, long sC)
{
    extern __shared__ char sm[];
    const u32 smb = smem_u32(sm);
    const int tid = threadIdx.x;
    const int wid = tid >> 5, lane = tid & 31;
    const int m0 = blockIdx.y * 128, n0 = blockIdx.x * 128;
    const int bz = blockIdx.z;

    const __nv_bfloat16* Arh = Ah_ + (size_t)bz * sA + (size_t)m0 * lda;
    const __nv_bfloat16* Arl = Al_ + (size_t)bz * sA + (size_t)m0 * lda;
    const __nv_bfloat16* Brh = Bh_ + (size_t)bz * sB + (size_t)n0 * ldb;
    const __nv_bfloat16* Brl = Bl_ + (size_t)bz * sB + (size_t)n0 * ldb;

    // loader mapping: 512 16B-chunks per tile, 2 per thread
    const int lrow0 = tid >> 2;           // idx = tid -> row
    const int lrow1 = (tid + 256) >> 2;
    const int lc0 = (tid & 3) * 16;       // byte col in tile
    const int lc1 = lc0;                  // (tid+256)&3 == tid&3

    // warp tile: warp_m in {0,1} (64 rows), warp_n in {0..3} (32 cols)
    const int warp_m = wid >> 2;
    const int warp_n = wid & 3;
    // ldmatrix lane addresses
    const int a_row = warp_m * 64 + (lane & 15);
    const int a_col = (lane >> 4) * 16;
    const int b_row = warp_n * 32 + ((lane >> 4) << 3) + (lane & 7);
    const int b_col = ((lane >> 3) & 1) * 16;

    float acc[4][4][4];
#pragma unroll
    for (int i = 0; i < 4; i++)
#pragma unroll
        for (int j = 0; j < 4; j++)
#pragma unroll
            for (int q = 0; q < 4; q++) acc[i][j][q] = 0.f;

    const int nch = K >> 5;

    // ---- loader lambda-ish macro ----
#define LOAD_CHUNK(cidx, buf)                                                      \
    do {                                                                           \
        const int kc_ = (cidx) << 5;                                               \
        const u32 sb_ = smb + (buf) * STAGEB;                                      \
        cp16(sb_ + 0 * TILEB + lrow0 * TPITCH + lc0,                               \
             (const char*)(Arh + (size_t)lrow0 * lda + kc_) + lc0);                \
        cp16(sb_ + 0 * TILEB + lrow1 * TPITCH + lc1,                               \
             (const char*)(Arh + (size_t)lrow1 * lda + kc_) + lc1);                \
        cp16(sb_ + 1 * TILEB + lrow0 * TPITCH + lc0,                               \
             (const char*)(Arl + (size_t)lrow0 * lda + kc_) + lc0);                \
        cp16(sb_ + 1 * TILEB + lrow1 * TPITCH + lc1,                               \
             (const char*)(Arl + (size_t)lrow1 * lda + kc_) + lc1);                \
        cp16(sb_ + 2 * TILEB + lrow0 * TPITCH + lc0,                               \
             (const char*)(Brh + (size_t)lrow0 * ldb + kc_) + lc0);                \
        cp16(sb_ + 2 * TILEB + lrow1 * TPITCH + lc1,                               \
             (const char*)(Brh + (size_t)lrow1 * ldb + kc_) + lc1);                \
        cp16(sb_ + 3 * TILEB + lrow0 * TPITCH + lc0,                               \
             (const char*)(Brl + (size_t)lrow0 * ldb + kc_) + lc0);                \
        cp16(sb_ + 3 * TILEB + lrow1 * TPITCH + lc1,                               \
             (const char*)(Brl + (size_t)lrow1 * ldb + kc_) + lc1);                \
        cp_commit();                                                               \
    } while (0)

    LOAD_CHUNK(0, 0);

    for (int c = 0; c < nch; c++) {
        const int buf = c & 1;
        if (c + 1 < nch) {
            LOAD_CHUNK(c + 1, buf ^ 1);
            cp_wait<1>();
        } else {
            cp_wait<0>();
        }
        __syncthreads();

        const u32 sb = smb + buf * STAGEB;
#pragma unroll
        for (int ks = 0; ks < 2; ks++) {
            u32 ah[4][4], al[4][4], bh[2][4], bl[2][4];
#pragma unroll
            for (int mi = 0; mi < 4; mi++) {
                u32 addr = sb + (a_row + mi * 16) * TPITCH + ks * 32 + a_col;
                ldm_x4(ah[mi], addr);
                ldm_x4(al[mi], addr + TILEB);
            }
#pragma unroll
            for (int nj2 = 0; nj2 < 2; nj2++) {
                u32 addr = sb + 2 * TILEB + (b_row + nj2 * 16) * TPITCH + ks * 32 + b_col;
                ldm_x4(bh[nj2], addr);
                ldm_x4(bl[nj2], addr + TILEB);
            }
#pragma unroll
            for (int mi = 0; mi < 4; mi++)
#pragma unroll
                for (int nj = 0; nj < 4; nj++) {
                    const u32* bhf = &bh[nj >> 1][(nj & 1) * 2];
                    const u32* blf = &bl[nj >> 1][(nj & 1) * 2];
                    mma16816(acc[mi][nj], ah[mi], bhf);   // hh
                    mma16816(acc[mi][nj], ah[mi], blf);   // hl
                    mma16816(acc[mi][nj], al[mi], bhf);   // lh
                }
        }
        __syncthreads();
    }

    // ---- epilogue ----
    const int erow = m0 + warp_m * 64 + (lane >> 2);
    const int ecol0 = n0 + warp_n * 32 + (lane & 3) * 2;
#pragma unroll
    for (int mi = 0; mi < 4; mi++) {
#pragma unroll
        for (int nj = 0; nj < 4; nj++) {
            float v0 = acc[mi][nj][0], v1 = acc[mi][nj][1];
            float v2 = acc[mi][nj][2], v3 = acc[mi][nj][3];
            const int col = ecol0 + nj * 8;
            if (ADD_BIAS) {
                float b0 = bias[col], b1 = bias[col + 1];
                v0 += b0; v1 += b1; v2 += b0; v3 += b1;
            }
            const size_t r0 = (size_t)bz * sC + (size_t)(erow + mi * 16) * ldc + col;
            const size_t r1 = r0 + (size_t)8 * ldc;
            if (!WRITE_SPLIT) {
                *(float2*)(Cf + r0) = make_float2(v0, v1);
                *(float2*)(Cf + r1) = make_float2(v2, v3);
            } else {
                u32 h0 = packbf(v1, v0);
                u32 l0 = packbf(v1 - hi_as_f32(h0), v0 - lo_as_f32(h0));
                u32 h1 = packbf(v3, v2);
                u32 l1 = packbf(v3 - hi_as_f32(h1), v2 - lo_as_f32(h1));
                *(u32*)(Ch + r0) = h0; *(u32*)(Cl + r0) = l0;
                *(u32*)(Ch + r1) = h1; *(u32*)(Cl + r1) = l1;
            }
        }
    }
#undef LOAD_CHUNK
}

// =====================================================================
// fp32 -> (hi, lo) bf16 split converter (K-major, element-wise)
// =====================================================================
__global__ void __launch_bounds__(256) convert_split(
    const float* __restrict__ x, __nv_bfloat16* __restrict__ h,
    __nv_bfloat16* __restrict__ l, int n4)
{
    int i = blockIdx.x * 256 + threadIdx.x;
    if (i >= n4) return;
    float4 v = ((const float4*)x)[i];
    u32 h0 = packbf(v.y, v.x);
    u32 h1 = packbf(v.w, v.z);
    u32 l0 = packbf(v.y - hi_as_f32(h0), v.x - lo_as_f32(h0));
    u32 l1 = packbf(v.w - hi_as_f32(h1), v.z - lo_as_f32(h1));
    ((uint2*)h)[i] = make_uint2(h0, h1);
    ((uint2*)l)[i] = make_uint2(l0, l1);
}

// =====================================================================
// Transpose + split: in fp32 [B][S][D] -> out hi/lo bf16 [B][D][S]
// =====================================================================
__global__ void __launch_bounds__(256) transpose_split(
    const float* __restrict__ x, __nv_bfloat16* __restrict__ th,
    __nv_bfloat16* __restrict__ tl)
{
    __shared__ float tile[32][33];
    const int tx = threadIdx.x & 31, ty = threadIdx.x >> 5;  // 32x8
    const int s0 = blockIdx.x * 32, d0 = blockIdx.y * 32, b = blockIdx.z;
    const float* src = x + (size_t)b * SN * DD;
#pragma unroll
    for (int j = 0; j < 4; j++)
        tile[ty + j * 8][tx] = src[(size_t)(s0 + ty + j * 8) * DD + d0 + tx];
    __syncthreads();
#pragma unroll
    for (int j = 0; j < 4; j++) {
        int d = d0 + ty + j * 8;
        int s = s0 + tx;
        float v = tile[tx][ty + j * 8];
        __nv_bfloat16 h = __float2bfloat16(v);
        float r = v - __bfloat162float(h);
        size_t off = (size_t)b * DD * SN + (size_t)d * SN + s;
        th[off] = h;
        tl[off] = __float2bfloat16(r);
    }
}

// =====================================================================
// Row softmax over S=2048 (fp32 in), writing split bf16 P
// =====================================================================
__global__ void __launch_bounds__(256) softmax_split(
    const float* __restrict__ P, __nv_bfloat16* __restrict__ Ph,
    __nv_bfloat16* __restrict__ Pl)
{
    __shared__ float red[8];
    const int tid = threadIdx.x;
    const int lane = tid & 31, warp = tid >> 5;
    const float* row = P + (size_t)blockIdx.x * SN;

    float4 v0 = ((const float4*)row)[tid];
    float4 v1 = ((const float4*)row)[tid + 256];

    float m = fmaxf(fmaxf(fmaxf(v0.x, v0.y), fmaxf(v0.z, v0.w)),
                    fmaxf(fmaxf(v1.x, v1.y), fmaxf(v1.z, v1.w)));
#pragma unroll
    for (int o = 16; o > 0; o >>= 1) m = fmaxf(m, __shfl_xor_sync(0xffffffffu, m, o));
    if (lane == 0) red[warp] = m;
    __syncthreads();
    float mall = red[0];
#pragma unroll
    for (int k = 1; k < 8; k++) mall = fmaxf(mall, red[k]);
    __syncthreads();

    v0.x = __expf(v0.x - mall); v0.y = __expf(v0.y - mall);
    v0.z = __expf(v0.z - mall); v0.w = __expf(v0.w - mall);
    v1.x = __expf(v1.x - mall); v1.y = __expf(v1.y - mall);
    v1.z = __expf(v1.z - mall); v1.w = __expf(v1.w - mall);

    float s = (v0.x + v0.y) + (v0.z + v0.w) + (v1.x + v1.y) + (v1.z + v1.w);
#pragma unroll
    for (int o = 16; o > 0; o >>= 1) s += __shfl_xor_sync(0xffffffffu, s, o);
    if (lane == 0) red[warp] = s;
    __syncthreads();
    float sall = red[0];
#pragma unroll
    for (int k = 1; k < 8; k++) sall += red[k];
    float inv = 1.0f / sall;

    v0.x *= inv; v0.y *= inv; v0.z *= inv; v0.w *= inv;
    v1.x *= inv; v1.y *= inv; v1.z *= inv; v1.w *= inv;

    uint2* ph2 = (uint2*)(Ph + (size_t)blockIdx.x * SN);
    uint2* pl2 = (uint2*)(Pl + (size_t)blockIdx.x * SN);
    {
        u32 h0 = packbf(v0.y, v0.x), h1 = packbf(v0.w, v0.z);
        u32 l0 = packbf(v0.y - hi_as_f32(h0), v0.x - lo_as_f32(h0));
        u32 l1 = packbf(v0.w - hi_as_f32(h1), v0.z - lo_as_f32(h1));
        ph2[tid] = make_uint2(h0, h1);
        pl2[tid] = make_uint2(l0, l1);
    }
    {
        u32 h0 = packbf(v1.y, v1.x), h1 = packbf(v1.w, v1.z);
        u32 l0 = packbf(v1.y - hi_as_f32(h0), v1.x - lo_as_f32(h0));
        u32 l1 = packbf(v1.w - hi_as_f32(h1), v1.z - lo_as_f32(h1));
        ph2[tid + 256] = make_uint2(h0, h1);
        pl2[tid + 256] = make_uint2(l0, l1);
    }
}

// =====================================================================
// kernel_launch
// =====================================================================
extern "C" void kernel_launch(void* const* d_in, const int* in_sizes, int n_in,
                              void* d_out, int out_size) {
    const float* main_in = (const float*)d_in[0];
    const float* attn_in = (const float*)d_in[1];
    const float* W_f = (const float*)d_in[2];
    const float* b_f = (const float*)d_in[3];
    float* out = (float*)d_out;

    __nv_bfloat16 *Qh, *Ql, *Ah, *Al, *Vth, *Vtl, *Wh, *Wl, *Kh, *Kl, *Ph, *Pl;
    float* P;
    cudaGetSymbolAddress((void**)&Qh, g_Qh);  cudaGetSymbolAddress((void**)&Ql, g_Ql);
    cudaGetSymbolAddress((void**)&Ah, g_Ah);  cudaGetSymbolAddress((void**)&Al, g_Al);
    cudaGetSymbolAddress((void**)&Vth, g_Vth); cudaGetSymbolAddress((void**)&Vtl, g_Vtl);
    cudaGetSymbolAddress((void**)&Wh, g_Wh);  cudaGetSymbolAddress((void**)&Wl, g_Wl);
    cudaGetSymbolAddress((void**)&Kh, g_Kh);  cudaGetSymbolAddress((void**)&Kl, g_Kl);
    cudaGetSymbolAddress((void**)&Ph, g_Ph);  cudaGetSymbolAddress((void**)&Pl, g_Pl);
    cudaGetSymbolAddress((void**)&P, g_P);

    // 0) splits + transpose
    {
        int n4q = (BB * TT * DD) / 4;
        convert_split<<<n4q / 256, 256>>>(main_in, Qh, Ql, n4q);
        int n4v = (BB * SN * DD) / 4;
        convert_split<<<n4v / 256, 256>>>(attn_in, Ah, Al, n4v);
        int n4w = (DD * DD) / 4;
        convert_split<<<(n4w + 255) / 256, 256>>>(W_f, Wh, Wl, n4w);
        dim3 tg(SN / 32, DD / 32, BB);
        transpose_split<<<tg, 256>>>(attn_in, Vth, Vtl);
    }

    cudaFuncSetAttribute(gemm_mma<true, true>,
                         cudaFuncAttributeMaxDynamicSharedMemorySize, SMEM_TOTAL);
    cudaFuncSetAttribute(gemm_mma<false, false>,
                         cudaFuncAttributeMaxDynamicSharedMemorySize, SMEM_TOTAL);

    // 1) keys = attn @ W^T + b -> split bf16. M=B*S=16384, N=512, K=512
    {
        dim3 grid(DD / 128, (BB * SN) / 128, 1);   // (4, 128, 1)
        gemm_mma<true, true><<<grid, 256, SMEM_TOTAL>>>(
            Ah, Al, Wh, Wl, b_f, nullptr, Kh, Kl,
            DD, DD, DD, DD, 0, 0, 0);
    }

    // 2) scores = Q @ keys^T -> fp32 P. per batch M=2048, N=2048, K=512
    {
        dim3 grid(SN / 128, TT / 128, BB);          // (16, 16, 8)
        gemm_mma<false, false><<<grid, 256, SMEM_TOTAL>>>(
            Qh, Ql, Kh, Kl, nullptr, P, nullptr, nullptr,
            DD, DD, DD, SN,
            (long)TT * DD, (long)SN * DD, (long)TT * SN);
    }

    // 3) softmax -> split bf16 P
    softmax_split<<<BB * TT, 256>>>(P, Ph, Pl);

    // 4) out = P @ Vt. per batch M=2048(T), N=512(D), K=2048(S)
    {
        dim3 grid(DD / 128, TT / 128, BB);          // (4, 16, 8)
        gemm_mma<false, false><<<grid, 256, SMEM_TOTAL>>>(
            Ph, Pl, Vth, Vtl, nullptr, out, nullptr, nullptr,
            SN, SN, SN, DD,
            (long)TT * SN, (long)DD * SN, (long)TT * DD);
    }
}

// round 5
// speedup vs baseline: 4.5060x; 1.0101x over previous
#include <cuda_runtime.h>
#include <cuda_bf16.h>
#include <cstdint>

// Problem constants: B=8, T=2048, S=2048, D=512
#define BB 8
#define TT 2048
#define SN 2048
#define DD 512

typedef uint32_t u32;
typedef uint64_t u64;

// ----------------- device scratch (allocation-free rules) -----------------
__device__ __nv_bfloat16 g_Qh[(size_t)BB * TT * DD];
__device__ __nv_bfloat16 g_Ql[(size_t)BB * TT * DD];
__device__ __nv_bfloat16 g_Ah[(size_t)BB * SN * DD];   // attn_input split (K-major)
__device__ __nv_bfloat16 g_Al[(size_t)BB * SN * DD];
__device__ __nv_bfloat16 g_Vth[(size_t)BB * DD * SN];  // attn_input transposed [B][D][S]
__device__ __nv_bfloat16 g_Vtl[(size_t)BB * DD * SN];
__device__ __nv_bfloat16 g_Wh[(size_t)DD * DD];
__device__ __nv_bfloat16 g_Wl[(size_t)DD * DD];
__device__ __nv_bfloat16 g_Kh[(size_t)BB * SN * DD];
__device__ __nv_bfloat16 g_Kl[(size_t)BB * SN * DD];
__device__ float g_P[(size_t)BB * TT * SN];            // 128 MB
__device__ __nv_bfloat16 g_Ph[(size_t)BB * TT * SN];   // 64 MB
__device__ __nv_bfloat16 g_Pl[(size_t)BB * TT * SN];   // 64 MB

// ----------------- helpers -----------------
__device__ __forceinline__ u32 smem_u32(const void* p) {
    u32 a;
    asm("{ .reg .u64 t; cvta.to.shared.u64 t, %1; cvt.u32.u64 %0, t; }" : "=r"(a) : "l"(p));
    return a;
}
// pack two fp32 -> bf16x2 word; lo half = second arg
__device__ __forceinline__ u32 packbf(float hi_elem, float lo_elem) {
    u32 r;
    asm("cvt.rn.bf16x2.f32 %0, %1, %2;" : "=r"(r) : "f"(hi_elem), "f"(lo_elem));
    return r;
}
__device__ __forceinline__ float lo_as_f32(u32 p) { return __uint_as_float(p << 16); }
__device__ __forceinline__ float hi_as_f32(u32 p) { return __uint_as_float(p & 0xFFFF0000u); }

__device__ __forceinline__ void cp16(u32 dst, const void* src) {
    asm volatile("cp.async.cg.shared.global [%0], [%1], 16;" :: "r"(dst), "l"(src));
}
__device__ __forceinline__ void cp_commit() {
    asm volatile("cp.async.commit_group;" ::: "memory");
}
template <int N>
__device__ __forceinline__ void cp_wait() {
    asm volatile("cp.async.wait_group %0;" :: "n"(N) : "memory");
}

__device__ __forceinline__ void ldm_x4(u32* r, u32 addr) {
    asm volatile("ldmatrix.sync.aligned.m8n8.x4.shared.b16 {%0,%1,%2,%3}, [%4];"
                 : "=r"(r[0]), "=r"(r[1]), "=r"(r[2]), "=r"(r[3]) : "r"(addr));
}
__device__ __forceinline__ void mma16816(float* d, const u32* a, const u32* b) {
    asm volatile(
        "mma.sync.aligned.m16n8k16.row.col.f32.bf16.bf16.f32 "
        "{%0,%1,%2,%3}, {%4,%5,%6,%7}, {%8,%9}, {%0,%1,%2,%3};"
        : "+f"(d[0]), "+f"(d[1]), "+f"(d[2]), "+f"(d[3])
        : "r"(a[0]), "r"(a[1]), "r"(a[2]), "r"(a[3]), "r"(b[0]), "r"(b[1]));
}

// ----------------- GEMM smem layout -----------------
// Tiles: 128 rows x 32 bf16 (64B data), row pitch 80B (conflict-free ldmatrix).
// Stage = {Ah, Al, Bh, Bl} = 40960B; 3 stages = 122880B.
#define TPITCH 80
#define TILEB (128 * TPITCH)
#define STAGEB (4 * TILEB)
#define NSTAGE 3
#define SMEM_TOTAL (NSTAGE * STAGEB)

// =====================================================================
// NT split-bf16 GEMM: C[m][n] = sum_k A[m][k]*B[n][k] (+bias[n])
//   A,B given as hi/lo bf16 row-major (K-major). 3 passes: hh+hl+lh.
//   CTA 128x128, 16 warps (32x32 warp tile), K-chunk 32, 3-stage cp.async.
// =====================================================================
template <bool WRITE_SPLIT, bool ADD_BIAS>
__global__ void __launch_bounds__(512, 1) gemm_mma(
    const __nv_bfloat16* __restrict__ Ah_, const __nv_bfloat16* __restrict__ Al_,
    const __nv_bfloat16* __restrict__ Bh_, const __nv_bfloat16* __restrict__ Bl_,
    const float* __restrict__ bias,
    float* __restrict__ Cf, __nv_bfloat16* __restrict__ Ch, __nv_bfloat16* __restrict__ Cl,
    int K, int lda, int ldb, int ldc,
    long sA, long sB, long sC)
{
    extern __shared__ char sm[];
    const u32 smb = smem_u32(sm);
    const int tid = threadIdx.x;
    const int wid = tid >> 5, lane = tid & 31;
    const int m0 = blockIdx.y * 128, n0 = blockIdx.x * 128;
    const int bz = blockIdx.z;

    const __nv_bfloat16* Arh = Ah_ + (size_t)bz * sA + (size_t)m0 * lda;
    const __nv_bfloat16* Arl = Al_ + (size_t)bz * sA + (size_t)m0 * lda;
    const __nv_bfloat16* Brh = Bh_ + (size_t)bz * sB + (size_t)n0 * ldb;
    const __nv_bfloat16* Brl = Bl_ + (size_t)bz * sB + (size_t)n0 * ldb;

    // loader: 512 threads, one 16B chunk per tile per thread
    const int lrow = tid >> 2;            // 0..127
    const int lc = (tid & 3) * 16;        // byte offset within 64B k-row

    // warp tile: warp_m in {0..3} (32 rows), warp_n in {0..3} (32 cols)
    const int warp_m = wid >> 2;
    const int warp_n = wid & 3;
    const int a_row = warp_m * 32 + (lane & 15);
    const int a_col = (lane >> 4) * 16;
    const int b_row = warp_n * 32 + ((lane >> 4) << 3) + (lane & 7);
    const int b_col = ((lane >> 3) & 1) * 16;

    float acc[2][4][4];
#pragma unroll
    for (int i = 0; i < 2; i++)
#pragma unroll
        for (int j = 0; j < 4; j++)
#pragma unroll
            for (int q = 0; q < 4; q++) acc[i][j][q] = 0.f;

    const int nch = K >> 5;

#define LOAD_CHUNK(cidx, st)                                                       \
    do {                                                                           \
        const int kc_ = (cidx) << 5;                                               \
        const u32 sb_ = smb + (st) * STAGEB;                                       \
        cp16(sb_ + 0 * TILEB + lrow * TPITCH + lc,                                 \
             (const char*)(Arh + (size_t)lrow * lda + kc_) + lc);                  \
        cp16(sb_ + 1 * TILEB + lrow * TPITCH + lc,                                 \
             (const char*)(Arl + (size_t)lrow * lda + kc_) + lc);                  \
        cp16(sb_ + 2 * TILEB + lrow * TPITCH + lc,                                 \
             (const char*)(Brh + (size_t)lrow * ldb + kc_) + lc);                  \
        cp16(sb_ + 3 * TILEB + lrow * TPITCH + lc,                                 \
             (const char*)(Brl + (size_t)lrow * ldb + kc_) + lc);                  \
        cp_commit();                                                               \
    } while (0)

    LOAD_CHUNK(0, 0);
    LOAD_CHUNK(1, 1);

    int st = 0, st_load = 2;
    for (int c = 0; c < nch; c++) {
        cp_wait<1>();
        __syncthreads();

        // issue load for chunk c+2 into the stage computed at iter c-1
        if (c + 2 < nch) {
            LOAD_CHUNK(c + 2, st_load);
            if (++st_load == NSTAGE) st_load = 0;
        } else {
            cp_commit();  // keep group numbering uniform
        }

        const u32 sb = smb + st * STAGEB;
#pragma unroll
        for (int ks = 0; ks < 2; ks++) {
            u32 ah[2][4], al[2][4], bh[2][4], bl[2][4];
#pragma unroll
            for (int mi = 0; mi < 2; mi++) {
                u32 addr = sb + (a_row + mi * 16) * TPITCH + ks * 32 + a_col;
                ldm_x4(ah[mi], addr);
                ldm_x4(al[mi], addr + TILEB);
            }
#pragma unroll
            for (int nj2 = 0; nj2 < 2; nj2++) {
                u32 addr = sb + 2 * TILEB + (b_row + nj2 * 16) * TPITCH + ks * 32 + b_col;
                ldm_x4(bh[nj2], addr);
                ldm_x4(bl[nj2], addr + TILEB);
            }
#pragma unroll
            for (int mi = 0; mi < 2; mi++)
#pragma unroll
                for (int nj = 0; nj < 4; nj++) {
                    const u32* bhf = &bh[nj >> 1][(nj & 1) * 2];
                    const u32* blf = &bl[nj >> 1][(nj & 1) * 2];
                    mma16816(acc[mi][nj], ah[mi], bhf);   // hh
                    mma16816(acc[mi][nj], ah[mi], blf);   // hl
                    mma16816(acc[mi][nj], al[mi], bhf);   // lh
                }
        }
        if (++st == NSTAGE) st = 0;
    }
#undef LOAD_CHUNK

    // ---- epilogue ----
    const int erow = m0 + warp_m * 32 + (lane >> 2);
    const int ecol0 = n0 + warp_n * 32 + (lane & 3) * 2;
#pragma unroll
    for (int mi = 0; mi < 2; mi++) {
#pragma unroll
        for (int nj = 0; nj < 4; nj++) {
            float v0 = acc[mi][nj][0], v1 = acc[mi][nj][1];
            float v2 = acc[mi][nj][2], v3 = acc[mi][nj][3];
            const int col = ecol0 + nj * 8;
            if (ADD_BIAS) {
                float b0 = bias[col], b1 = bias[col + 1];
                v0 += b0; v1 += b1; v2 += b0; v3 += b1;
            }
            const size_t r0 = (size_t)bz * sC + (size_t)(erow + mi * 16) * ldc + col;
            const size_t r1 = r0 + (size_t)8 * ldc;
            if (!WRITE_SPLIT) {
                *(float2*)(Cf + r0) = make_float2(v0, v1);
                *(float2*)(Cf + r1) = make_float2(v2, v3);
            } else {
                u32 h0 = packbf(v1, v0);
                u32 l0 = packbf(v1 - hi_as_f32(h0), v0 - lo_as_f32(h0));
                u32 h1 = packbf(v3, v2);
                u32 l1 = packbf(v3 - hi_as_f32(h1), v2 - lo_as_f32(h1));
                *(u32*)(Ch + r0) = h0; *(u32*)(Cl + r0) = l0;
                *(u32*)(Ch + r1) = h1; *(u32*)(Cl + r1) = l1;
            }
        }
    }
}

// =====================================================================
// fp32 -> (hi, lo) bf16 split converter
// =====================================================================
__global__ void __launch_bounds__(256) convert_split(
    const float* __restrict__ x, __nv_bfloat16* __restrict__ h,
    __nv_bfloat16* __restrict__ l, int n4)
{
    int i = blockIdx.x * 256 + threadIdx.x;
    if (i >= n4) return;
    float4 v = ((const float4*)x)[i];
    u32 h0 = packbf(v.y, v.x);
    u32 h1 = packbf(v.w, v.z);
    u32 l0 = packbf(v.y - hi_as_f32(h0), v.x - lo_as_f32(h0));
    u32 l1 = packbf(v.w - hi_as_f32(h1), v.z - lo_as_f32(h1));
    ((uint2*)h)[i] = make_uint2(h0, h1);
    ((uint2*)l)[i] = make_uint2(l0, l1);
}

// =====================================================================
// Transpose + split: in fp32 [B][S][D] -> out hi/lo bf16 [B][D][S]
// =====================================================================
__global__ void __launch_bounds__(256) transpose_split(
    const float* __restrict__ x, __nv_bfloat16* __restrict__ th,
    __nv_bfloat16* __restrict__ tl)
{
    __shared__ float tile[32][33];
    const int tx = threadIdx.x & 31, ty = threadIdx.x >> 5;  // 32x8
    const int s0 = blockIdx.x * 32, d0 = blockIdx.y * 32, b = blockIdx.z;
    const float* src = x + (size_t)b * SN * DD;
#pragma unroll
    for (int j = 0; j < 4; j++)
        tile[ty + j * 8][tx] = src[(size_t)(s0 + ty + j * 8) * DD + d0 + tx];
    __syncthreads();
#pragma unroll
    for (int j = 0; j < 4; j++) {
        int d = d0 + ty + j * 8;
        int s = s0 + tx;
        float v = tile[tx][ty + j * 8];
        __nv_bfloat16 h = __float2bfloat16(v);
        float r = v - __bfloat162float(h);
        size_t off = (size_t)b * DD * SN + (size_t)d * SN + s;
        th[off] = h;
        tl[off] = __float2bfloat16(r);
    }
}

// =====================================================================
// Row softmax over S=2048 (fp32 in), writing split bf16 P
// =====================================================================
__global__ void __launch_bounds__(256) softmax_split(
    const float* __restrict__ P, __nv_bfloat16* __restrict__ Ph,
    __nv_bfloat16* __restrict__ Pl)
{
    __shared__ float red[8];
    const int tid = threadIdx.x;
    const int lane = tid & 31, warp = tid >> 5;
    const float* row = P + (size_t)blockIdx.x * SN;

    float4 v0 = ((const float4*)row)[tid];
    float4 v1 = ((const float4*)row)[tid + 256];

    float m = fmaxf(fmaxf(fmaxf(v0.x, v0.y), fmaxf(v0.z, v0.w)),
                    fmaxf(fmaxf(v1.x, v1.y), fmaxf(v1.z, v1.w)));
#pragma unroll
    for (int o = 16; o > 0; o >>= 1) m = fmaxf(m, __shfl_xor_sync(0xffffffffu, m, o));
    if (lane == 0) red[warp] = m;
    __syncthreads();
    float mall = red[0];
#pragma unroll
    for (int k = 1; k < 8; k++) mall = fmaxf(mall, red[k]);
    __syncthreads();

    v0.x = __expf(v0.x - mall); v0.y = __expf(v0.y - mall);
    v0.z = __expf(v0.z - mall); v0.w = __expf(v0.w - mall);
    v1.x = __expf(v1.x - mall); v1.y = __expf(v1.y - mall);
    v1.z = __expf(v1.z - mall); v1.w = __expf(v1.w - mall);

    float s = (v0.x + v0.y) + (v0.z + v0.w) + (v1.x + v1.y) + (v1.z + v1.w);
#pragma unroll
    for (int o = 16; o > 0; o >>= 1) s += __shfl_xor_sync(0xffffffffu, s, o);
    if (lane == 0) red[warp] = s;
    __syncthreads();
    float sall = red[0];
#pragma unroll
    for (int k = 1; k < 8; k++) sall += red[k];
    float inv = 1.0f / sall;

    v0.x *= inv; v0.y *= inv; v0.z *= inv; v0.w *= inv;
    v1.x *= inv; v1.y *= inv; v1.z *= inv; v1.w *= inv;

    uint2* ph2 = (uint2*)(Ph + (size_t)blockIdx.x * SN);
    uint2* pl2 = (uint2*)(Pl + (size_t)blockIdx.x * SN);
    {
        u32 h0 = packbf(v0.y, v0.x), h1 = packbf(v0.w, v0.z);
        u32 l0 = packbf(v0.y - hi_as_f32(h0), v0.x - lo_as_f32(h0));
        u32 l1 = packbf(v0.w - hi_as_f32(h1), v0.z - lo_as_f32(h1));
        ph2[tid] = make_uint2(h0, h1);
        pl2[tid] = make_uint2(l0, l1);
    }
    {
        u32 h0 = packbf(v1.y, v1.x), h1 = packbf(v1.w, v1.z);
        u32 l0 = packbf(v1.y - hi_as_f32(h0), v1.x - lo_as_f32(h0));
        u32 l1 = packbf(v1.w - hi_as_f32(h1), v1.z - lo_as_f32(h1));
        ph2[tid + 256] = make_uint2(h0, h1);
        pl2[tid + 256] = make_uint2(l0, l1);
    }
}

// =====================================================================
// kernel_launch
// =====================================================================
extern "C" void kernel_launch(void* const* d_in, const int* in_sizes, int n_in,
                              void* d_out, int out_size) {
    const float* main_in = (const float*)d_in[0];
    const float* attn_in = (const float*)d_in[1];
    const float* W_f = (const float*)d_in[2];
    const float* b_f = (const float*)d_in[3];
    float* out = (float*)d_out;

    __nv_bfloat16 *Qh, *Ql, *Ah, *Al, *Vth, *Vtl, *Wh, *Wl, *Kh, *Kl, *Ph, *Pl;
    float* P;
    cudaGetSymbolAddress((void**)&Qh, g_Qh);  cudaGetSymbolAddress((void**)&Ql, g_Ql);
    cudaGetSymbolAddress((void**)&Ah, g_Ah);  cudaGetSymbolAddress((void**)&Al, g_Al);
    cudaGetSymbolAddress((void**)&Vth, g_Vth); cudaGetSymbolAddress((void**)&Vtl, g_Vtl);
    cudaGetSymbolAddress((void**)&Wh, g_Wh);  cudaGetSymbolAddress((void**)&Wl, g_Wl);
    cudaGetSymbolAddress((void**)&Kh, g_Kh);  cudaGetSymbolAddress((void**)&Kl, g_Kl);
    cudaGetSymbolAddress((void**)&Ph, g_Ph);  cudaGetSymbolAddress((void**)&Pl, g_Pl);
    cudaGetSymbolAddress((void**)&P, g_P);

    // 0) splits + transpose
    {
        int n4q = (BB * TT * DD) / 4;
        convert_split<<<n4q / 256, 256>>>(main_in, Qh, Ql, n4q);
        int n4v = (BB * SN * DD) / 4;
        convert_split<<<n4v / 256, 256>>>(attn_in, Ah, Al, n4v);
        int n4w = (DD * DD) / 4;
        convert_split<<<(n4w + 255) / 256, 256>>>(W_f, Wh, Wl, n4w);
        dim3 tg(SN / 32, DD / 32, BB);
        transpose_split<<<tg, 256>>>(attn_in, Vth, Vtl);
    }

    cudaFuncSetAttribute(gemm_mma<true, true>,
                         cudaFuncAttributeMaxDynamicSharedMemorySize, SMEM_TOTAL);
    cudaFuncSetAttribute(gemm_mma<false, false>,
                         cudaFuncAttributeMaxDynamicSharedMemorySize, SMEM_TOTAL);

    // 1) keys = attn @ W^T + b -> split bf16. M=B*S=16384, N=512, K=512
    {
        dim3 grid(DD / 128, (BB * SN) / 128, 1);   // (4, 128, 1)
        gemm_mma<true, true><<<grid, 512, SMEM_TOTAL>>>(
            Ah, Al, Wh, Wl, b_f, nullptr, Kh, Kl,
            DD, DD, DD, DD, 0, 0, 0);
    }

    // 2) scores = Q @ keys^T -> fp32 P. per batch M=2048, N=2048, K=512
    {
        dim3 grid(SN / 128, TT / 128, BB);          // (16, 16, 8)
        gemm_mma<false, false><<<grid, 512, SMEM_TOTAL>>>(
            Qh, Ql, Kh, Kl, nullptr, P, nullptr, nullptr,
            DD, DD, DD, SN,
            (long)TT * DD, (long)SN * DD, (long)TT * SN);
    }

    // 3) softmax -> split bf16 P
    softmax_split<<<BB * TT, 256>>>(P, Ph, Pl);

    // 4) out = P @ Vt. per batch M=2048(T), N=512(D), K=2048(S)
    {
        dim3 grid(DD / 128, TT / 128, BB);          // (4, 16, 8)
        gemm_mma<false, false><<<grid, 512, SMEM_TOTAL>>>(
            Ph, Pl, Vth, Vtl, nullptr, out, nullptr, nullptr,
            SN, SN, SN, DD,
            (long)TT * SN, (long)DD * SN, (long)TT * DD);
    }
}

// round 6
// speedup vs baseline: 5.1546x; 1.1439x over previous
#include <cuda_runtime.h>
#include <cuda_fp16.h>
#include <cstdint>

// Problem constants: B=8, T=2048, S=2048, D=512
#define BB 8
#define TT 2048
#define SN 2048
#define DD 512

typedef uint32_t u32;
typedef uint64_t u64;

// ----------------- device scratch (allocation-free rules) -----------------
__device__ __half g_Qh[(size_t)BB * TT * DD];
__device__ __half g_Ql[(size_t)BB * TT * DD];
__device__ __half g_Ah[(size_t)BB * SN * DD];   // attn_input split (K-major)
__device__ __half g_Al[(size_t)BB * SN * DD];
__device__ __half g_Vt[(size_t)BB * DD * SN];   // attn_input transposed [B][D][S], hi limb only
__device__ __half g_Wh[(size_t)DD * DD];
__device__ __half g_Wl[(size_t)DD * DD];
__device__ __half g_Kh[(size_t)BB * SN * DD];
__device__ __half g_Kl[(size_t)BB * SN * DD];
__device__ float g_P[(size_t)BB * TT * SN];     // 128 MB
__device__ __half g_Ph[(size_t)BB * TT * SN];   // 64 MB
__device__ __half g_Pl[(size_t)BB * TT * SN];   // 64 MB

// ----------------- helpers -----------------
__device__ __forceinline__ u32 smem_u32(const void* p) {
    u32 a;
    asm("{ .reg .u64 t; cvta.to.shared.u64 t, %1; cvt.u32.u64 %0, t; }" : "=r"(a) : "l"(p));
    return a;
}
// pack two fp32 -> half2 word; first arg = high half, second = low half
__device__ __forceinline__ u32 packh(float hi_elem, float lo_elem) {
    __half2 h = __floats2half2_rn(lo_elem, hi_elem);
    return *(u32*)&h;
}
__device__ __forceinline__ float lo_h2f(u32 p) {
    __half2 h = *(__half2*)&p;
    return __half2float(__low2half(h));
}
__device__ __forceinline__ float hi_h2f(u32 p) {
    __half2 h = *(__half2*)&p;
    return __half2float(__high2half(h));
}

__device__ __forceinline__ void cp16(u32 dst, const void* src) {
    asm volatile("cp.async.cg.shared.global [%0], [%1], 16;" :: "r"(dst), "l"(src));
}
__device__ __forceinline__ void cp_commit() {
    asm volatile("cp.async.commit_group;" ::: "memory");
}
template <int N>
__device__ __forceinline__ void cp_wait() {
    asm volatile("cp.async.wait_group %0;" :: "n"(N) : "memory");
}

__device__ __forceinline__ void ldm_x4(u32* r, u32 addr) {
    asm volatile("ldmatrix.sync.aligned.m8n8.x4.shared.b16 {%0,%1,%2,%3}, [%4];"
                 : "=r"(r[0]), "=r"(r[1]), "=r"(r[2]), "=r"(r[3]) : "r"(addr));
}
__device__ __forceinline__ void mma16816(float* d, const u32* a, const u32* b) {
    asm volatile(
        "mma.sync.aligned.m16n8k16.row.col.f32.f16.f16.f32 "
        "{%0,%1,%2,%3}, {%4,%5,%6,%7}, {%8,%9}, {%0,%1,%2,%3};"
        : "+f"(d[0]), "+f"(d[1]), "+f"(d[2]), "+f"(d[3])
        : "r"(a[0]), "r"(a[1]), "r"(a[2]), "r"(a[3]), "r"(b[0]), "r"(b[1]));
}

// ----------------- GEMM smem layout -----------------
// Tiles: 128 rows x 32 fp16 (64B data), row pitch 80B (conflict-free ldmatrix).
#define TPITCH 80
#define TILEB (128 * TPITCH)
#define NSTAGE 3

// =====================================================================
// NT split-fp16 GEMM: C[m][n] = sum_k A[m][k]*B(n,k) (+bias[n])
//   A always 2 limbs (hi/lo).
//   BLIMBS=2: B 2 limbs, 3 passes (hh, hl, lh), pass-major ordering.
//   BLIMBS=1: B 1 limb,  2 passes (ah*b, al*b).
//   CTA 128x128, 16 warps (32x32 warp tile), K-chunk 32, 3-stage cp.async.
// =====================================================================
template <int BLIMBS, bool WRITE_SPLIT, bool ADD_BIAS>
__global__ void __launch_bounds__(512, 1) gemm_mma(
    const __half* __restrict__ Ah_, const __half* __restrict__ Al_,
    const __half* __restrict__ Bh_, const __half* __restrict__ Bl_,
    const float* __restrict__ bias,
    float* __restrict__ Cf, __half* __restrict__ Ch, __half* __restrict__ Cl,
    int K, int lda, int ldb, int ldc,
    long sA, long sB, long sC)
{
    constexpr int NT = 2 + BLIMBS;             // tiles per stage
    constexpr int STAGEB = NT * TILEB;

    extern __shared__ char sm[];
    const u32 smb = smem_u32(sm);
    const int tid = threadIdx.x;
    const int wid = tid >> 5, lane = tid & 31;
    const int m0 = blockIdx.y * 128, n0 = blockIdx.x * 128;
    const int bz = blockIdx.z;

    const __half* Arh = Ah_ + (size_t)bz * sA + (size_t)m0 * lda;
    const __half* Arl = Al_ + (size_t)bz * sA + (size_t)m0 * lda;
    const __half* Brh = Bh_ + (size_t)bz * sB + (size_t)n0 * ldb;
    const __half* Brl = (BLIMBS == 2) ? (Bl_ + (size_t)bz * sB + (size_t)n0 * ldb) : nullptr;

    // loader: 512 threads, one 16B chunk per tile per thread
    const int lrow = tid >> 2;            // 0..127
    const int lc = (tid & 3) * 16;        // byte offset within 64B k-row

    // warp tile: warp_m in {0..3} (32 rows), warp_n in {0..3} (32 cols)
    const int warp_m = wid >> 2;
    const int warp_n = wid & 3;
    const int a_row = warp_m * 32 + (lane & 15);
    const int a_col = (lane >> 4) * 16;
    const int b_row = warp_n * 32 + ((lane >> 4) << 3) + (lane & 7);
    const int b_col = ((lane >> 3) & 1) * 16;

    float acc[2][4][4];
#pragma unroll
    for (int i = 0; i < 2; i++)
#pragma unroll
        for (int j = 0; j < 4; j++)
#pragma unroll
            for (int q = 0; q < 4; q++) acc[i][j][q] = 0.f;

    const int nch = K >> 5;

#define LOAD_CHUNK(cidx, st)                                                       \
    do {                                                                           \
        const int kc_ = (cidx) << 5;                                               \
        const u32 sb_ = smb + (st) * STAGEB;                                       \
        cp16(sb_ + 0 * TILEB + lrow * TPITCH + lc,                                 \
             (const char*)(Arh + (size_t)lrow * lda + kc_) + lc);                  \
        cp16(sb_ + 1 * TILEB + lrow * TPITCH + lc,                                 \
             (const char*)(Arl + (size_t)lrow * lda + kc_) + lc);                  \
        cp16(sb_ + 2 * TILEB + lrow * TPITCH + lc,                                 \
             (const char*)(Brh + (size_t)lrow * ldb + kc_) + lc);                  \
        if (BLIMBS == 2)                                                           \
            cp16(sb_ + 3 * TILEB + lrow * TPITCH + lc,                             \
                 (const char*)(Brl + (size_t)lrow * ldb + kc_) + lc);              \
        cp_commit();                                                               \
    } while (0)

    LOAD_CHUNK(0, 0);
    LOAD_CHUNK(1, 1);

    int st = 0, st_load = 2;
    for (int c = 0; c < nch; c++) {
        cp_wait<1>();
        __syncthreads();

        if (c + 2 < nch) {
            LOAD_CHUNK(c + 2, st_load);
            if (++st_load == NSTAGE) st_load = 0;
        } else {
            cp_commit();  // keep group numbering uniform
        }

        const u32 sb = smb + st * STAGEB;
#pragma unroll
        for (int ks = 0; ks < 2; ks++) {
            u32 ah[2][4], al[2][4], bh[2][4], bl[2][4];
#pragma unroll
            for (int mi = 0; mi < 2; mi++) {
                u32 addr = sb + (a_row + mi * 16) * TPITCH + ks * 32 + a_col;
                ldm_x4(ah[mi], addr);
                ldm_x4(al[mi], addr + TILEB);
            }
#pragma unroll
            for (int nj2 = 0; nj2 < 2; nj2++) {
                u32 addr = sb + 2 * TILEB + (b_row + nj2 * 16) * TPITCH + ks * 32 + b_col;
                ldm_x4(bh[nj2], addr);
                if (BLIMBS == 2) ldm_x4(bl[nj2], addr + TILEB);
            }

            // ---- pass-major ordering: consecutive MMAs hit different accs ----
            // pass 0: Ah * Bh
#pragma unroll
            for (int mi = 0; mi < 2; mi++)
#pragma unroll
                for (int nj = 0; nj < 4; nj++)
                    mma16816(acc[mi][nj], ah[mi], &bh[nj >> 1][(nj & 1) * 2]);
            // pass 1: Ah * Bl  (BLIMBS==2)  or  Al * B (BLIMBS==1)
            if (BLIMBS == 2) {
#pragma unroll
                for (int mi = 0; mi < 2; mi++)
#pragma unroll
                    for (int nj = 0; nj < 4; nj++)
                        mma16816(acc[mi][nj], ah[mi], &bl[nj >> 1][(nj & 1) * 2]);
                // pass 2: Al * Bh
#pragma unroll
                for (int mi = 0; mi < 2; mi++)
#pragma unroll
                    for (int nj = 0; nj < 4; nj++)
                        mma16816(acc[mi][nj], al[mi], &bh[nj >> 1][(nj & 1) * 2]);
            } else {
#pragma unroll
                for (int mi = 0; mi < 2; mi++)
#pragma unroll
                    for (int nj = 0; nj < 4; nj++)
                        mma16816(acc[mi][nj], al[mi], &bh[nj >> 1][(nj & 1) * 2]);
            }
        }
        if (++st == NSTAGE) st = 0;
    }
#undef LOAD_CHUNK

    // ---- epilogue ----
    const int erow = m0 + warp_m * 32 + (lane >> 2);
    const int ecol0 = n0 + warp_n * 32 + (lane & 3) * 2;
#pragma unroll
    for (int mi = 0; mi < 2; mi++) {
#pragma unroll
        for (int nj = 0; nj < 4; nj++) {
            float v0 = acc[mi][nj][0], v1 = acc[mi][nj][1];
            float v2 = acc[mi][nj][2], v3 = acc[mi][nj][3];
            const int col = ecol0 + nj * 8;
            if (ADD_BIAS) {
                float b0 = bias[col], b1 = bias[col + 1];
                v0 += b0; v1 += b1; v2 += b0; v3 += b1;
            }
            const size_t r0 = (size_t)bz * sC + (size_t)(erow + mi * 16) * ldc + col;
            const size_t r1 = r0 + (size_t)8 * ldc;
            if (!WRITE_SPLIT) {
                *(float2*)(Cf + r0) = make_float2(v0, v1);
                *(float2*)(Cf + r1) = make_float2(v2, v3);
            } else {
                u32 h0 = packh(v1, v0);
                u32 l0 = packh(v1 - hi_h2f(h0), v0 - lo_h2f(h0));
                u32 h1 = packh(v3, v2);
                u32 l1 = packh(v3 - hi_h2f(h1), v2 - lo_h2f(h1));
                *(u32*)(Ch + r0) = h0; *(u32*)(Cl + r0) = l0;
                *(u32*)(Ch + r1) = h1; *(u32*)(Cl + r1) = l1;
            }
        }
    }
}

// =====================================================================
// fp32 -> (hi, lo) fp16 split converter
// =====================================================================
__global__ void __launch_bounds__(256) convert_split(
    const float* __restrict__ x, __half* __restrict__ h,
    __half* __restrict__ l, int n4)
{
    int i = blockIdx.x * 256 + threadIdx.x;
    if (i >= n4) return;
    float4 v = ((const float4*)x)[i];
    u32 h0 = packh(v.y, v.x);
    u32 h1 = packh(v.w, v.z);
    u32 l0 = packh(v.y - hi_h2f(h0), v.x - lo_h2f(h0));
    u32 l1 = packh(v.w - hi_h2f(h1), v.z - lo_h2f(h1));
    ((uint2*)h)[i] = make_uint2(h0, h1);
    ((uint2*)l)[i] = make_uint2(l0, l1);
}

// =====================================================================
// Transpose: in fp32 [B][S][D] -> out fp16 [B][D][S] (hi limb only)
// =====================================================================
__global__ void __launch_bounds__(256) transpose_half(
    const float* __restrict__ x, __half* __restrict__ th)
{
    __shared__ float tile[32][33];
    const int tx = threadIdx.x & 31, ty = threadIdx.x >> 5;  // 32x8
    const int s0 = blockIdx.x * 32, d0 = blockIdx.y * 32, b = blockIdx.z;
    const float* src = x + (size_t)b * SN * DD;
#pragma unroll
    for (int j = 0; j < 4; j++)
        tile[ty + j * 8][tx] = src[(size_t)(s0 + ty + j * 8) * DD + d0 + tx];
    __syncthreads();
#pragma unroll
    for (int j = 0; j < 4; j++) {
        int d = d0 + ty + j * 8;
        int s = s0 + tx;
        th[(size_t)b * DD * SN + (size_t)d * SN + s] = __float2half_rn(tile[tx][ty + j * 8]);
    }
}

// =====================================================================
// Row softmax over S=2048 (fp32 in), writing split fp16 P
// =====================================================================
__global__ void __launch_bounds__(256) softmax_split(
    const float* __restrict__ P, __half* __restrict__ Ph,
    __half* __restrict__ Pl)
{
    __shared__ float red[8];
    const int tid = threadIdx.x;
    const int lane = tid & 31, warp = tid >> 5;
    const float* row = P + (size_t)blockIdx.x * SN;

    float4 v0 = ((const float4*)row)[tid];
    float4 v1 = ((const float4*)row)[tid + 256];

    float m = fmaxf(fmaxf(fmaxf(v0.x, v0.y), fmaxf(v0.z, v0.w)),
                    fmaxf(fmaxf(v1.x, v1.y), fmaxf(v1.z, v1.w)));
#pragma unroll
    for (int o = 16; o > 0; o >>= 1) m = fmaxf(m, __shfl_xor_sync(0xffffffffu, m, o));
    if (lane == 0) red[warp] = m;
    __syncthreads();
    float mall = red[0];
#pragma unroll
    for (int k = 1; k < 8; k++) mall = fmaxf(mall, red[k]);
    __syncthreads();

    v0.x = __expf(v0.x - mall); v0.y = __expf(v0.y - mall);
    v0.z = __expf(v0.z - mall); v0.w = __expf(v0.w - mall);
    v1.x = __expf(v1.x - mall); v1.y = __expf(v1.y - mall);
    v1.z = __expf(v1.z - mall); v1.w = __expf(v1.w - mall);

    float s = (v0.x + v0.y) + (v0.z + v0.w) + (v1.x + v1.y) + (v1.z + v1.w);
#pragma unroll
    for (int o = 16; o > 0; o >>= 1) s += __shfl_xor_sync(0xffffffffu, s, o);
    if (lane == 0) red[warp] = s;
    __syncthreads();
    float sall = red[0];
#pragma unroll
    for (int k = 1; k < 8; k++) sall += red[k];
    float inv = 1.0f / sall;

    v0.x *= inv; v0.y *= inv; v0.z *= inv; v0.w *= inv;
    v1.x *= inv; v1.y *= inv; v1.z *= inv; v1.w *= inv;

    uint2* ph2 = (uint2*)(Ph + (size_t)blockIdx.x * SN);
    uint2* pl2 = (uint2*)(Pl + (size_t)blockIdx.x * SN);
    {
        u32 h0 = packh(v0.y, v0.x), h1 = packh(v0.w, v0.z);
        u32 l0 = packh(v0.y - hi_h2f(h0), v0.x - lo_h2f(h0));
        u32 l1 = packh(v0.w - hi_h2f(h1), v0.z - lo_h2f(h1));
        ph2[tid] = make_uint2(h0, h1);
        pl2[tid] = make_uint2(l0, l1);
    }
    {
        u32 h0 = packh(v1.y, v1.x), h1 = packh(v1.w, v1.z);
        u32 l0 = packh(v1.y - hi_h2f(h0), v1.x - lo_h2f(h0));
        u32 l1 = packh(v1.w - hi_h2f(h1), v1.z - lo_h2f(h1));
        ph2[tid + 256] = make_uint2(h0, h1);
        pl2[tid + 256] = make_uint2(l0, l1);
    }
}

// =====================================================================
// kernel_launch
// =====================================================================
extern "C" void kernel_launch(void* const* d_in, const int* in_sizes, int n_in,
                              void* d_out, int out_size) {
    const float* main_in = (const float*)d_in[0];
    const float* attn_in = (const float*)d_in[1];
    const float* W_f = (const float*)d_in[2];
    const float* b_f = (const float*)d_in[3];
    float* out = (float*)d_out;

    __half *Qh, *Ql, *Ah, *Al, *Vt, *Wh, *Wl, *Kh, *Kl, *Ph, *Pl;
    float* P;
    cudaGetSymbolAddress((void**)&Qh, g_Qh);  cudaGetSymbolAddress((void**)&Ql, g_Ql);
    cudaGetSymbolAddress((void**)&Ah, g_Ah);  cudaGetSymbolAddress((void**)&Al, g_Al);
    cudaGetSymbolAddress((void**)&Vt, g_Vt);
    cudaGetSymbolAddress((void**)&Wh, g_Wh);  cudaGetSymbolAddress((void**)&Wl, g_Wl);
    cudaGetSymbolAddress((void**)&Kh, g_Kh);  cudaGetSymbolAddress((void**)&Kl, g_Kl);
    cudaGetSymbolAddress((void**)&Ph, g_Ph);  cudaGetSymbolAddress((void**)&Pl, g_Pl);
    cudaGetSymbolAddress((void**)&P, g_P);

    // 0) splits + transpose
    {
        int n4q = (BB * TT * DD) / 4;
        convert_split<<<n4q / 256, 256>>>(main_in, Qh, Ql, n4q);
        int n4v = (BB * SN * DD) / 4;
        convert_split<<<n4v / 256, 256>>>(attn_in, Ah, Al, n4v);
        int n4w = (DD * DD) / 4;
        convert_split<<<(n4w + 255) / 256, 256>>>(W_f, Wh, Wl, n4w);
        dim3 tg(SN / 32, DD / 32, BB);
        transpose_half<<<tg, 256>>>(attn_in, Vt);
    }

    constexpr int SMEM2 = NSTAGE * 4 * TILEB;  // BLIMBS=2: 122880
    constexpr int SMEM1 = NSTAGE * 3 * TILEB;  // BLIMBS=1: 92160
    cudaFuncSetAttribute(gemm_mma<2, true, true>,
                         cudaFuncAttributeMaxDynamicSharedMemorySize, SMEM2);
    cudaFuncSetAttribute(gemm_mma<2, false, false>,
                         cudaFuncAttributeMaxDynamicSharedMemorySize, SMEM2);
    cudaFuncSetAttribute(gemm_mma<1, false, false>,
                         cudaFuncAttributeMaxDynamicSharedMemorySize, SMEM1);

    // 1) keys = attn @ W^T + b -> split fp16. M=B*S=16384, N=512, K=512
    {
        dim3 grid(DD / 128, (BB * SN) / 128, 1);   // (4, 128, 1)
        gemm_mma<2, true, true><<<grid, 512, SMEM2>>>(
            Ah, Al, Wh, Wl, b_f, nullptr, Kh, Kl,
            DD, DD, DD, DD, 0, 0, 0);
    }

    // 2) scores = Q @ keys^T -> fp32 P. per batch M=2048, N=2048, K=512
    {
        dim3 grid(SN / 128, TT / 128, BB);          // (16, 16, 8)
        gemm_mma<2, false, false><<<grid, 512, SMEM2>>>(
            Qh, Ql, Kh, Kl, nullptr, P, nullptr, nullptr,
            DD, DD, DD, SN,
            (long)TT * DD, (long)SN * DD, (long)TT * SN);
    }

    // 3) softmax -> split fp16 P
    softmax_split<<<BB * TT, 256>>>(P, Ph, Pl);

    // 4) out = P @ Vt. per batch M=2048(T), N=512(D), K=2048(S), 2 passes
    {
        dim3 grid(DD / 128, TT / 128, BB);          // (4, 16, 8)
        gemm_mma<1, false, false><<<grid, 512, SMEM1>>>(
            Ph, Pl, Vt, nullptr, nullptr, out, nullptr, nullptr,
            SN, SN, SN, DD,
            (long)TT * SN, (long)DD * SN, (long)TT * DD);
    }
}

// round 7
// speedup vs baseline: 5.8835x; 1.1414x over previous
#include <cuda_runtime.h>
#include <cuda_fp16.h>
#include <cstdint>

// Problem constants: B=8, T=2048, S=2048, D=512
#define BB 8
#define TT 2048
#define SN 2048
#define DD 512

typedef uint32_t u32;
typedef uint64_t u64;

// ----------------- device scratch (allocation-free rules) -----------------
__device__ __half g_Qh[(size_t)BB * TT * DD];
__device__ __half g_Ql[(size_t)BB * TT * DD];
__device__ __half g_Ah[(size_t)BB * SN * DD];   // attn_input split (K-major)
__device__ __half g_Al[(size_t)BB * SN * DD];
__device__ __half g_Vt[(size_t)BB * DD * SN];   // attn_input transposed [B][D][S], hi limb only
__device__ __half g_Wh[(size_t)DD * DD];
__device__ __half g_Wl[(size_t)DD * DD];
__device__ __half g_Kh[(size_t)BB * SN * DD];
__device__ __half g_Kl[(size_t)BB * SN * DD];
__device__ float g_P[(size_t)BB * TT * SN];     // 128 MB
__device__ __half g_Ph[(size_t)BB * TT * SN];   // 64 MB

// ----------------- helpers -----------------
__device__ __forceinline__ u32 smem_u32(const void* p) {
    u32 a;
    asm("{ .reg .u64 t; cvta.to.shared.u64 t, %1; cvt.u32.u64 %0, t; }" : "=r"(a) : "l"(p));
    return a;
}
// pack two fp32 -> half2 word; first arg = high half, second = low half
__device__ __forceinline__ u32 packh(float hi_elem, float lo_elem) {
    __half2 h = __floats2half2_rn(lo_elem, hi_elem);
    return *(u32*)&h;
}
__device__ __forceinline__ float lo_h2f(u32 p) {
    __half2 h = *(__half2*)&p;
    return __half2float(__low2half(h));
}
__device__ __forceinline__ float hi_h2f(u32 p) {
    __half2 h = *(__half2*)&p;
    return __half2float(__high2half(h));
}

__device__ __forceinline__ void cp16(u32 dst, const void* src) {
    asm volatile("cp.async.cg.shared.global [%0], [%1], 16;" :: "r"(dst), "l"(src));
}
__device__ __forceinline__ void cp_commit() {
    asm volatile("cp.async.commit_group;" ::: "memory");
}
template <int N>
__device__ __forceinline__ void cp_wait() {
    asm volatile("cp.async.wait_group %0;" :: "n"(N) : "memory");
}

__device__ __forceinline__ void ldm_x4(u32* r, u32 addr) {
    asm volatile("ldmatrix.sync.aligned.m8n8.x4.shared.b16 {%0,%1,%2,%3}, [%4];"
                 : "=r"(r[0]), "=r"(r[1]), "=r"(r[2]), "=r"(r[3]) : "r"(addr));
}
__device__ __forceinline__ void mma16816(float* d, const u32* a, const u32* b) {
    asm volatile(
        "mma.sync.aligned.m16n8k16.row.col.f32.f16.f16.f32 "
        "{%0,%1,%2,%3}, {%4,%5,%6,%7}, {%8,%9}, {%0,%1,%2,%3};"
        : "+f"(d[0]), "+f"(d[1]), "+f"(d[2]), "+f"(d[3])
        : "r"(a[0]), "r"(a[1]), "r"(a[2]), "r"(a[3]), "r"(b[0]), "r"(b[1]));
}

// ----------------- GEMM smem layout -----------------
// Tiles: 128 rows x 32 fp16 (64B data), row pitch 80B (conflict-free ldmatrix).
#define TPITCH 80
#define TILEB (128 * TPITCH)
#define NSTAGE 3

// =====================================================================
// NT split-fp16 GEMM: C[m][n] = sum_k A[m][k]*B(n,k) (+bias[n])
//   ALIMBS/BLIMBS in {1,2}. Passes (pass-major, pa+pb<2):
//     2,2 -> hh, hl, lh ; 2,1 -> ah*b, al*b ; 1,1 -> single pass.
//   CTA 128x128, 16 warps (32x32 warp tile), K-chunk 32, 3-stage cp.async.
// =====================================================================
template <int ALIMBS, int BLIMBS, bool WRITE_SPLIT, bool ADD_BIAS>
__global__ void __launch_bounds__(512, 1) gemm_mma(
    const __half* __restrict__ Ah_, const __half* __restrict__ Al_,
    const __half* __restrict__ Bh_, const __half* __restrict__ Bl_,
    const float* __restrict__ bias,
    float* __restrict__ Cf, __half* __restrict__ Ch, __half* __restrict__ Cl,
    int K, int lda, int ldb, int ldc,
    long sA, long sB, long sC)
{
    constexpr int NT = ALIMBS + BLIMBS;        // tiles per stage
    constexpr int STAGEB = NT * TILEB;
    constexpr int BOFF = ALIMBS * TILEB;       // B tiles offset within stage

    extern __shared__ char sm[];
    const u32 smb = smem_u32(sm);
    const int tid = threadIdx.x;
    const int wid = tid >> 5, lane = tid & 31;
    const int m0 = blockIdx.y * 128, n0 = blockIdx.x * 128;
    const int bz = blockIdx.z;

    const __half* Arh = Ah_ + (size_t)bz * sA + (size_t)m0 * lda;
    const __half* Arl = (ALIMBS == 2) ? (Al_ + (size_t)bz * sA + (size_t)m0 * lda) : nullptr;
    const __half* Brh = Bh_ + (size_t)bz * sB + (size_t)n0 * ldb;
    const __half* Brl = (BLIMBS == 2) ? (Bl_ + (size_t)bz * sB + (size_t)n0 * ldb) : nullptr;

    // loader: 512 threads, one 16B chunk per tile per thread
    const int lrow = tid >> 2;            // 0..127
    const int lc = (tid & 3) * 16;        // byte offset within 64B k-row

    // warp tile: warp_m in {0..3} (32 rows), warp_n in {0..3} (32 cols)
    const int warp_m = wid >> 2;
    const int warp_n = wid & 3;
    const int a_row = warp_m * 32 + (lane & 15);
    const int a_col = (lane >> 4) * 16;
    const int b_row = warp_n * 32 + ((lane >> 4) << 3) + (lane & 7);
    const int b_col = ((lane >> 3) & 1) * 16;

    float acc[2][4][4];
#pragma unroll
    for (int i = 0; i < 2; i++)
#pragma unroll
        for (int j = 0; j < 4; j++)
#pragma unroll
            for (int q = 0; q < 4; q++) acc[i][j][q] = 0.f;

    const int nch = K >> 5;

#define LOAD_CHUNK(cidx, st)                                                       \
    do {                                                                           \
        const int kc_ = (cidx) << 5;                                               \
        const u32 sb_ = smb + (st) * STAGEB;                                       \
        cp16(sb_ + 0 * TILEB + lrow * TPITCH + lc,                                 \
             (const char*)(Arh + (size_t)lrow * lda + kc_) + lc);                  \
        if (ALIMBS == 2)                                                           \
            cp16(sb_ + 1 * TILEB + lrow * TPITCH + lc,                             \
                 (const char*)(Arl + (size_t)lrow * lda + kc_) + lc);              \
        cp16(sb_ + BOFF + lrow * TPITCH + lc,                                      \
             (const char*)(Brh + (size_t)lrow * ldb + kc_) + lc);                  \
        if (BLIMBS == 2)                                                           \
            cp16(sb_ + BOFF + TILEB + lrow * TPITCH + lc,                          \
                 (const char*)(Brl + (size_t)lrow * ldb + kc_) + lc);              \
        cp_commit();                                                               \
    } while (0)

    LOAD_CHUNK(0, 0);
    LOAD_CHUNK(1, 1);

    int st = 0, st_load = 2;
    for (int c = 0; c < nch; c++) {
        cp_wait<1>();
        __syncthreads();

        if (c + 2 < nch) {
            LOAD_CHUNK(c + 2, st_load);
            if (++st_load == NSTAGE) st_load = 0;
        } else {
            cp_commit();  // keep group numbering uniform
        }

        const u32 sb = smb + st * STAGEB;
#pragma unroll
        for (int ks = 0; ks < 2; ks++) {
            u32 ah[2][4], al[2][4], bh[2][4], bl[2][4];
#pragma unroll
            for (int mi = 0; mi < 2; mi++) {
                u32 addr = sb + (a_row + mi * 16) * TPITCH + ks * 32 + a_col;
                ldm_x4(ah[mi], addr);
                if (ALIMBS == 2) ldm_x4(al[mi], addr + TILEB);
            }
#pragma unroll
            for (int nj2 = 0; nj2 < 2; nj2++) {
                u32 addr = sb + BOFF + (b_row + nj2 * 16) * TPITCH + ks * 32 + b_col;
                ldm_x4(bh[nj2], addr);
                if (BLIMBS == 2) ldm_x4(bl[nj2], addr + TILEB);
            }

            // ---- pass-major ordering ----
            // pass 0: Ah * Bh
#pragma unroll
            for (int mi = 0; mi < 2; mi++)
#pragma unroll
                for (int nj = 0; nj < 4; nj++)
                    mma16816(acc[mi][nj], ah[mi], &bh[nj >> 1][(nj & 1) * 2]);
            if (BLIMBS == 2) {
                // pass 1: Ah * Bl
#pragma unroll
                for (int mi = 0; mi < 2; mi++)
#pragma unroll
                    for (int nj = 0; nj < 4; nj++)
                        mma16816(acc[mi][nj], ah[mi], &bl[nj >> 1][(nj & 1) * 2]);
            }
            if (ALIMBS == 2) {
                // pass 2: Al * Bh
#pragma unroll
                for (int mi = 0; mi < 2; mi++)
#pragma unroll
                    for (int nj = 0; nj < 4; nj++)
                        mma16816(acc[mi][nj], al[mi], &bh[nj >> 1][(nj & 1) * 2]);
            }
        }
        if (++st == NSTAGE) st = 0;
    }
#undef LOAD_CHUNK

    // ---- epilogue ----
    const int erow = m0 + warp_m * 32 + (lane >> 2);
    const int ecol0 = n0 + warp_n * 32 + (lane & 3) * 2;
#pragma unroll
    for (int mi = 0; mi < 2; mi++) {
#pragma unroll
        for (int nj = 0; nj < 4; nj++) {
            float v0 = acc[mi][nj][0], v1 = acc[mi][nj][1];
            float v2 = acc[mi][nj][2], v3 = acc[mi][nj][3];
            const int col = ecol0 + nj * 8;
            if (ADD_BIAS) {
                float b0 = bias[col], b1 = bias[col + 1];
                v0 += b0; v1 += b1; v2 += b0; v3 += b1;
            }
            const size_t r0 = (size_t)bz * sC + (size_t)(erow + mi * 16) * ldc + col;
            const size_t r1 = r0 + (size_t)8 * ldc;
            if (!WRITE_SPLIT) {
                *(float2*)(Cf + r0) = make_float2(v0, v1);
                *(float2*)(Cf + r1) = make_float2(v2, v3);
            } else {
                u32 h0 = packh(v1, v0);
                u32 l0 = packh(v1 - hi_h2f(h0), v0 - lo_h2f(h0));
                u32 h1 = packh(v3, v2);
                u32 l1 = packh(v3 - hi_h2f(h1), v2 - lo_h2f(h1));
                *(u32*)(Ch + r0) = h0; *(u32*)(Cl + r0) = l0;
                *(u32*)(Ch + r1) = h1; *(u32*)(Cl + r1) = l1;
            }
        }
    }
}

// =====================================================================
// fp32 -> (hi, lo) fp16 split converter
// =====================================================================
__global__ void __launch_bounds__(256) convert_split(
    const float* __restrict__ x, __half* __restrict__ h,
    __half* __restrict__ l, int n4)
{
    int i = blockIdx.x * 256 + threadIdx.x;
    if (i >= n4) return;
    float4 v = ((const float4*)x)[i];
    u32 h0 = packh(v.y, v.x);
    u32 h1 = packh(v.w, v.z);
    u32 l0 = packh(v.y - hi_h2f(h0), v.x - lo_h2f(h0));
    u32 l1 = packh(v.w - hi_h2f(h1), v.z - lo_h2f(h1));
    ((uint2*)h)[i] = make_uint2(h0, h1);
    ((uint2*)l)[i] = make_uint2(l0, l1);
}

// =====================================================================
// Transpose: in fp32 [B][S][D] -> out fp16 [B][D][S] (hi limb only)
// =====================================================================
__global__ void __launch_bounds__(256) transpose_half(
    const float* __restrict__ x, __half* __restrict__ th)
{
    __shared__ float tile[32][33];
    const int tx = threadIdx.x & 31, ty = threadIdx.x >> 5;  // 32x8
    const int s0 = blockIdx.x * 32, d0 = blockIdx.y * 32, b = blockIdx.z;
    const float* src = x + (size_t)b * SN * DD;
#pragma unroll
    for (int j = 0; j < 4; j++)
        tile[ty + j * 8][tx] = src[(size_t)(s0 + ty + j * 8) * DD + d0 + tx];
    __syncthreads();
#pragma unroll
    for (int j = 0; j < 4; j++) {
        int d = d0 + ty + j * 8;
        int s = s0 + tx;
        th[(size_t)b * DD * SN + (size_t)d * SN + s] = __float2half_rn(tile[tx][ty + j * 8]);
    }
}

// =====================================================================
// Row softmax over S=2048 (fp32 in), writing fp16 P (hi limb only)
// =====================================================================
__global__ void __launch_bounds__(256) softmax_half(
    const float* __restrict__ P, __half* __restrict__ Ph)
{
    __shared__ float red[8];
    const int tid = threadIdx.x;
    const int lane = tid & 31, warp = tid >> 5;
    const float* row = P + (size_t)blockIdx.x * SN;

    float4 v0 = ((const float4*)row)[tid];
    float4 v1 = ((const float4*)row)[tid + 256];

    float m = fmaxf(fmaxf(fmaxf(v0.x, v0.y), fmaxf(v0.z, v0.w)),
                    fmaxf(fmaxf(v1.x, v1.y), fmaxf(v1.z, v1.w)));
#pragma unroll
    for (int o = 16; o > 0; o >>= 1) m = fmaxf(m, __shfl_xor_sync(0xffffffffu, m, o));
    if (lane == 0) red[warp] = m;
    __syncthreads();
    float mall = red[0];
#pragma unroll
    for (int k = 1; k < 8; k++) mall = fmaxf(mall, red[k]);
    __syncthreads();

    v0.x = __expf(v0.x - mall); v0.y = __expf(v0.y - mall);
    v0.z = __expf(v0.z - mall); v0.w = __expf(v0.w - mall);
    v1.x = __expf(v1.x - mall); v1.y = __expf(v1.y - mall);
    v1.z = __expf(v1.z - mall); v1.w = __expf(v1.w - mall);

    float s = (v0.x + v0.y) + (v0.z + v0.w) + (v1.x + v1.y) + (v1.z + v1.w);
#pragma unroll
    for (int o = 16; o > 0; o >>= 1) s += __shfl_xor_sync(0xffffffffu, s, o);
    if (lane == 0) red[warp] = s;
    __syncthreads();
    float sall = red[0];
#pragma unroll
    for (int k = 1; k < 8; k++) sall += red[k];
    float inv = 1.0f / sall;

    v0.x *= inv; v0.y *= inv; v0.z *= inv; v0.w *= inv;
    v1.x *= inv; v1.y *= inv; v1.z *= inv; v1.w *= inv;

    uint2* ph2 = (uint2*)(Ph + (size_t)blockIdx.x * SN);
    ph2[tid]       = make_uint2(packh(v0.y, v0.x), packh(v0.w, v0.z));
    ph2[tid + 256] = make_uint2(packh(v1.y, v1.x), packh(v1.w, v1.z));
}

// =====================================================================
// kernel_launch
// =====================================================================
extern "C" void kernel_launch(void* const* d_in, const int* in_sizes, int n_in,
                              void* d_out, int out_size) {
    const float* main_in = (const float*)d_in[0];
    const float* attn_in = (const float*)d_in[1];
    const float* W_f = (const float*)d_in[2];
    const float* b_f = (const float*)d_in[3];
    float* out = (float*)d_out;

    __half *Qh, *Ql, *Ah, *Al, *Vt, *Wh, *Wl, *Kh, *Kl, *Ph;
    float* P;
    cudaGetSymbolAddress((void**)&Qh, g_Qh);  cudaGetSymbolAddress((void**)&Ql, g_Ql);
    cudaGetSymbolAddress((void**)&Ah, g_Ah);  cudaGetSymbolAddress((void**)&Al, g_Al);
    cudaGetSymbolAddress((void**)&Vt, g_Vt);
    cudaGetSymbolAddress((void**)&Wh, g_Wh);  cudaGetSymbolAddress((void**)&Wl, g_Wl);
    cudaGetSymbolAddress((void**)&Kh, g_Kh);  cudaGetSymbolAddress((void**)&Kl, g_Kl);
    cudaGetSymbolAddress((void**)&Ph, g_Ph);
    cudaGetSymbolAddress((void**)&P, g_P);

    // 0) splits + transpose
    {
        int n4q = (BB * TT * DD) / 4;
        convert_split<<<n4q / 256, 256>>>(main_in, Qh, Ql, n4q);
        int n4v = (BB * SN * DD) / 4;
        convert_split<<<n4v / 256, 256>>>(attn_in, Ah, Al, n4v);
        int n4w = (DD * DD) / 4;
        convert_split<<<(n4w + 255) / 256, 256>>>(W_f, Wh, Wl, n4w);
        dim3 tg(SN / 32, DD / 32, BB);
        transpose_half<<<tg, 256>>>(attn_in, Vt);
    }

    constexpr int SMEM22 = NSTAGE * 4 * TILEB;  // 122880
    constexpr int SMEM11 = NSTAGE * 2 * TILEB;  // 61440
    cudaFuncSetAttribute(gemm_mma<2, 2, true, true>,
                         cudaFuncAttributeMaxDynamicSharedMemorySize, SMEM22);
    cudaFuncSetAttribute(gemm_mma<2, 2, false, false>,
                         cudaFuncAttributeMaxDynamicSharedMemorySize, SMEM22);
    cudaFuncSetAttribute(gemm_mma<1, 1, false, false>,
                         cudaFuncAttributeMaxDynamicSharedMemorySize, SMEM11);

    // 1) keys = attn @ W^T + b -> split fp16. M=B*S=16384, N=512, K=512
    {
        dim3 grid(DD / 128, (BB * SN) / 128, 1);   // (4, 128, 1)
        gemm_mma<2, 2, true, true><<<grid, 512, SMEM22>>>(
            Ah, Al, Wh, Wl, b_f, nullptr, Kh, Kl,
            DD, DD, DD, DD, 0, 0, 0);
    }

    // 2) scores = Q @ keys^T -> fp32 P. per batch M=2048, N=2048, K=512
    {
        dim3 grid(SN / 128, TT / 128, BB);          // (16, 16, 8)
        gemm_mma<2, 2, false, false><<<grid, 512, SMEM22>>>(
            Qh, Ql, Kh, Kl, nullptr, P, nullptr, nullptr,
            DD, DD, DD, SN,
            (long)TT * DD, (long)SN * DD, (long)TT * SN);
    }

    // 3) softmax -> fp16 Ph
    softmax_half<<<BB * TT, 256>>>(P, Ph);

    // 4) out = Ph @ Vt. per batch M=2048(T), N=512(D), K=2048(S), single pass
    {
        dim3 grid(DD / 128, TT / 128, BB);          // (4, 16, 8)
        gemm_mma<1, 1, false, false><<<grid, 512, SMEM11>>>(
            Ph, nullptr, Vt, nullptr, nullptr, out, nullptr, nullptr,
            SN, SN, SN, DD,
            (long)TT * SN, (long)DD * SN, (long)TT * DD);
    }
}